// round 1
// baseline (speedup 1.0000x reference)
#include <cuda_runtime.h>

#define NN 100000
#define NE 1600000
#define F  128
#define NG 64
#define OUTF 64

// ---------------- scratch (static device globals: allowed) ----------------
__device__ float g_buf0[NN * F];      // transformed features y = x@W
__device__ float g_buf1[NN * F];      // layer output h
__device__ int   g_deg[NN];
__device__ int   g_rowoff[NN + 1];
__device__ int   g_cursor[NN];
__device__ int   g_csr[NE];
__device__ float g_invdeg[NN];
__device__ int   g_gstart[NG + 1];
__device__ float g_hg[NG * F];

// ---------------- CSR build ----------------
__global__ void k_init() {
    int i = blockIdx.x * blockDim.x + threadIdx.x;
    if (i < NN) g_deg[i] = 0;
    if (i <= NG) g_gstart[i] = (i == NG) ? NN : -1;
}

__global__ void k_deg(const int* __restrict__ dst) {
    int e = blockIdx.x * blockDim.x + threadIdx.x;
    if (e < NE) atomicAdd(&g_deg[dst[e]], 1);
}

// single-block exclusive scan over degrees -> row offsets, cursors, 1/deg
__global__ void k_scan() {
    __shared__ int ssum[1024];
    int tid = threadIdx.x;
    const int CH = (NN + 1023) / 1024;          // 98
    int beg = tid * CH;
    int end = min(beg + CH, NN);
    int s = 0;
    for (int i = beg; i < end; i++) s += g_deg[i];
    ssum[tid] = s;
    __syncthreads();
    for (int off = 1; off < 1024; off <<= 1) {
        int v = (tid >= off) ? ssum[tid - off] : 0;
        __syncthreads();
        ssum[tid] += v;
        __syncthreads();
    }
    int run = (tid == 0) ? 0 : ssum[tid - 1];
    for (int i = beg; i < end; i++) {
        g_rowoff[i] = run;
        g_cursor[i] = run;
        int d = g_deg[i];
        g_invdeg[i] = 1.0f / (float)max(d, 1);
        run += d;
    }
    if (tid == 1023) g_rowoff[NN] = NE;
}

__global__ void k_scatter(const int* __restrict__ src, const int* __restrict__ dst) {
    int e = blockIdx.x * blockDim.x + threadIdx.x;
    if (e < NE) {
        int p = atomicAdd(&g_cursor[dst[e]], 1);
        g_csr[p] = src[e];
    }
}

// ---------------- per-graph boundaries (graph_ids are sorted) ----------------
__global__ void k_gb(const int* __restrict__ gid) {
    int i = blockIdx.x * blockDim.x + threadIdx.x;
    if (i < NN) {
        int g = gid[i];
        if (i == 0 || gid[i - 1] != g) g_gstart[g] = i;
    }
}
__global__ void k_gfix() {
    if (threadIdx.x == 0) {
        for (int g = NG - 1; g >= 0; g--)
            if (g_gstart[g] < 0) g_gstart[g] = g_gstart[g + 1];
    }
}

// ---------------- dense GEMM: Y[M,128] = X[M,128] @ W[128,128] (no bias) ----
// block tile: 128 rows x 64 cols, 256 threads, 4x8 register blocking.
// Operands stream through L1 (X rows: 64KB/tile; W: 64KB total) -> FFMA-bound.
__global__ __launch_bounds__(256) void k_gemm(const float* __restrict__ X,
                                              const float* __restrict__ W,
                                              float* __restrict__ Y) {
    int base = blockIdx.x * 128;
    int tid  = threadIdx.x;
    int tx   = tid & 7;          // col-group 0..7
    int ty   = tid >> 3;         // row 0..31
    int colb = blockIdx.y * 64 + tx * 8;

    const float4* __restrict__ W4 = (const float4*)W;

    const float* __restrict__ xr[4];
    int rows[4];
#pragma unroll
    for (int i = 0; i < 4; i++) {
        int r = base + ty + 32 * i;
        rows[i] = r;
        xr[i] = X + (size_t)min(r, NN - 1) * F;   // clamp: safe read, store guarded
    }

    float acc[4][8];
#pragma unroll
    for (int i = 0; i < 4; i++)
#pragma unroll
        for (int j = 0; j < 8; j++) acc[i][j] = 0.0f;

#pragma unroll 8
    for (int k = 0; k < F; k++) {
        float a0 = xr[0][k], a1 = xr[1][k], a2 = xr[2][k], a3 = xr[3][k];
        float4 b0 = W4[k * 32 + (colb >> 2)];
        float4 b1 = W4[k * 32 + (colb >> 2) + 1];
        float bb[8] = {b0.x, b0.y, b0.z, b0.w, b1.x, b1.y, b1.z, b1.w};
#pragma unroll
        for (int j = 0; j < 8; j++) {
            acc[0][j] = fmaf(a0, bb[j], acc[0][j]);
            acc[1][j] = fmaf(a1, bb[j], acc[1][j]);
            acc[2][j] = fmaf(a2, bb[j], acc[2][j]);
            acc[3][j] = fmaf(a3, bb[j], acc[3][j]);
        }
    }

#pragma unroll
    for (int i = 0; i < 4; i++) {
        if (rows[i] < NN) {
            float4* o = (float4*)(Y + (size_t)rows[i] * F + colb);
            o[0] = make_float4(acc[i][0], acc[i][1], acc[i][2], acc[i][3]);
            o[1] = make_float4(acc[i][4], acc[i][5], acc[i][6], acc[i][7]);
        }
    }
}

// ---------------- aggregation: H[v] = relu(Y[v] + invdeg[v]*sum_nbr Y + b) --
// warp per node, float4 per lane; gather rows are L2-resident (51MB table).
__global__ __launch_bounds__(256) void k_agg(const float* __restrict__ Y,
                                             const float* __restrict__ bias,
                                             float* __restrict__ H) {
    int gw   = (blockIdx.x * blockDim.x + threadIdx.x) >> 5;
    int lane = threadIdx.x & 31;
    if (gw >= NN) return;

    int beg = g_rowoff[gw];
    int end = g_rowoff[gw + 1];
    const float4* __restrict__ Y4 = (const float4*)Y;

    float4 acc = make_float4(0.f, 0.f, 0.f, 0.f);
    int e = beg;
    for (; e + 1 < end; e += 2) {
        int s0 = g_csr[e];
        int s1 = g_csr[e + 1];
        float4 v0 = Y4[(size_t)s0 * 32 + lane];
        float4 v1 = Y4[(size_t)s1 * 32 + lane];
        acc.x += v0.x + v1.x;
        acc.y += v0.y + v1.y;
        acc.z += v0.z + v1.z;
        acc.w += v0.w + v1.w;
    }
    if (e < end) {
        int s = g_csr[e];
        float4 v = Y4[(size_t)s * 32 + lane];
        acc.x += v.x; acc.y += v.y; acc.z += v.z; acc.w += v.w;
    }

    float inv = g_invdeg[gw];
    float4 yv = Y4[(size_t)gw * 32 + lane];
    float4 bb = ((const float4*)bias)[lane];
    float4 h;
    h.x = fmaxf(fmaf(acc.x, inv, yv.x) + bb.x, 0.f);
    h.y = fmaxf(fmaf(acc.y, inv, yv.y) + bb.y, 0.f);
    h.z = fmaxf(fmaf(acc.z, inv, yv.z) + bb.z, 0.f);
    h.w = fmaxf(fmaf(acc.w, inv, yv.w) + bb.w, 0.f);
    ((float4*)H)[(size_t)gw * 32 + lane] = h;
}

// ---------------- per-graph mean pooling ----------------
__global__ void k_pool(const float* __restrict__ H, float* __restrict__ out) {
    int g   = blockIdx.x;
    int tid = threadIdx.x;          // 512
    int col = tid & 127;
    int sub = tid >> 7;             // 0..3
    int s = g_gstart[g];
    int e = g_gstart[g + 1];
    float p = 0.0f;
    for (int r = s + sub; r < e; r += 4) p += H[(size_t)r * F + col];
    __shared__ float sm[512];
    sm[tid] = p;
    __syncthreads();
    if (tid < 128) {
        float sum = sm[tid] + sm[tid + 128] + sm[tid + 256] + sm[tid + 384];
        int cnt = e - s;
        float mean = sum / (float)max(cnt, 1);
        g_hg[g * F + col] = mean;
        out[g * F + col]  = mean;
    }
}

// ---------------- decoder: out = relu(hg@Wd1+bd1)@Wd2+bd2 ----------------
__global__ void k_dec(const float* __restrict__ Wd1, const float* __restrict__ bd1,
                      const float* __restrict__ Wd2, const float* __restrict__ bd2,
                      float* __restrict__ out) {
    int g = blockIdx.x;
    int tid = threadIdx.x;          // 128
    __shared__ float hgs[F], ts[F];
    hgs[tid] = g_hg[g * F + tid];
    __syncthreads();
    float s0 = 0.f, s1 = 0.f, s2 = 0.f, s3 = 0.f;
#pragma unroll 8
    for (int k = 0; k < F; k += 4) {
        s0 = fmaf(hgs[k],     Wd1[(k)     * F + tid], s0);
        s1 = fmaf(hgs[k + 1], Wd1[(k + 1) * F + tid], s1);
        s2 = fmaf(hgs[k + 2], Wd1[(k + 2) * F + tid], s2);
        s3 = fmaf(hgs[k + 3], Wd1[(k + 3) * F + tid], s3);
    }
    ts[tid] = fmaxf((s0 + s1) + (s2 + s3) + bd1[tid], 0.f);
    __syncthreads();
    if (tid < OUTF) {
        float o0 = 0.f, o1 = 0.f, o2 = 0.f, o3 = 0.f;
#pragma unroll 8
        for (int k = 0; k < F; k += 4) {
            o0 = fmaf(ts[k],     Wd2[(k)     * OUTF + tid], o0);
            o1 = fmaf(ts[k + 1], Wd2[(k + 1) * OUTF + tid], o1);
            o2 = fmaf(ts[k + 2], Wd2[(k + 2) * OUTF + tid], o2);
            o3 = fmaf(ts[k + 3], Wd2[(k + 3) * OUTF + tid], o3);
        }
        out[NG * F + g * OUTF + tid] = (o0 + o1) + (o2 + o3) + bd2[tid];
    }
}

// ---------------- launch ----------------
extern "C" void kernel_launch(void* const* d_in, const int* in_sizes, int n_in,
                              void* d_out, int out_size) {
    const float* feat = (const float*)d_in[0];
    const int*   src  = (const int*)d_in[1];
    const int*   dst  = (const int*)d_in[2];
    const int*   gid  = (const int*)d_in[3];
    const float* W1   = (const float*)d_in[4];
    const float* b1   = (const float*)d_in[5];
    const float* W2   = (const float*)d_in[6];
    const float* b2   = (const float*)d_in[7];
    const float* Wd1  = (const float*)d_in[8];
    const float* bd1  = (const float*)d_in[9];
    const float* Wd2  = (const float*)d_in[10];
    const float* bd2  = (const float*)d_in[11];
    float* out = (float*)d_out;

    float *buf0, *buf1;
    cudaGetSymbolAddress((void**)&buf0, g_buf0);
    cudaGetSymbolAddress((void**)&buf1, g_buf1);

    // graph structure (identical both layers): CSR by dst + graph ranges
    k_init<<<(NN + 255) / 256, 256>>>();
    k_deg<<<(NE + 255) / 256, 256>>>(dst);
    k_scan<<<1, 1024>>>();
    k_scatter<<<(NE + 255) / 256, 256>>>(src, dst);
    k_gb<<<(NN + 255) / 256, 256>>>(gid);
    k_gfix<<<1, 32>>>();

    dim3 ggrid((NN + 127) / 128, 2);

    // layer 1: y = x@W1 ; h1 = relu(y + mean_nbr(y) + b1)
    k_gemm<<<ggrid, 256>>>(feat, W1, buf0);
    k_agg<<<(NN * 32 + 255) / 256, 256>>>(buf0, b1, buf1);

    // layer 2
    k_gemm<<<ggrid, 256>>>(buf1, W2, buf0);
    k_agg<<<(NN * 32 + 255) / 256, 256>>>(buf0, b2, buf1);

    // pooling + decoder
    k_pool<<<NG, 512>>>(buf1, out);
    k_dec<<<NG, 128>>>(Wd1, bd1, Wd2, bd2, out);
}

// round 2
// speedup vs baseline: 1.6360x; 1.6360x over previous
#include <cuda_runtime.h>
#include <cuda_bf16.h>
#include <cstdint>

#define NN 100000
#define NE 1600000
#define F  128
#define NG 64
#define OUTF 64

// ---------------- scratch ----------------
__device__ float g_buf0[NN * F];              // Y = X@W (fp32, self term)
__device__ float g_buf1[NN * F];              // layer output H
__device__ __nv_bfloat16 g_bufbf[NN * F];     // bf16 copy of Y for gathers
__device__ int   g_deg[NN];
__device__ int   g_rowoff[NN + 1];
__device__ int   g_cursor[NN];
__device__ int   g_csr[NE];
__device__ float g_invdeg[NN];
__device__ int   g_gstart[NG + 1];
__device__ float g_hg[NG * F];
__device__ float g_part[NG * 8 * F];

// ---------------- CSR build ----------------
__global__ void k_init() {
    int i = blockIdx.x * blockDim.x + threadIdx.x;
    if (i < NN) g_deg[i] = 0;
    if (i <= NG) g_gstart[i] = (i == NG) ? NN : -1;
}

__global__ void k_deg(const int* __restrict__ dst) {
    int e = blockIdx.x * blockDim.x + threadIdx.x;
    if (e < NE) atomicAdd(&g_deg[dst[e]], 1);
}

__global__ void k_scan() {
    __shared__ int ssum[1024];
    int tid = threadIdx.x;
    const int CH = (NN + 1023) / 1024;
    int beg = tid * CH;
    int end = min(beg + CH, NN);
    int s = 0;
    for (int i = beg; i < end; i++) s += g_deg[i];
    ssum[tid] = s;
    __syncthreads();
    for (int off = 1; off < 1024; off <<= 1) {
        int v = (tid >= off) ? ssum[tid - off] : 0;
        __syncthreads();
        ssum[tid] += v;
        __syncthreads();
    }
    int run = (tid == 0) ? 0 : ssum[tid - 1];
    for (int i = beg; i < end; i++) {
        g_rowoff[i] = run;
        g_cursor[i] = run;
        int d = g_deg[i];
        g_invdeg[i] = 1.0f / (float)max(d, 1);
        run += d;
    }
    if (tid == 1023) g_rowoff[NN] = NE;
}

__global__ void k_scatter(const int* __restrict__ src, const int* __restrict__ dst) {
    int e = blockIdx.x * blockDim.x + threadIdx.x;
    if (e < NE) {
        int p = atomicAdd(&g_cursor[dst[e]], 1);
        g_csr[p] = src[e];
    }
}

__global__ void k_gb(const int* __restrict__ gid) {
    int i = blockIdx.x * blockDim.x + threadIdx.x;
    if (i < NN) {
        int g = gid[i];
        if (i == 0 || gid[i - 1] != g) g_gstart[g] = i;
    }
}
__global__ void k_gfix() {
    if (threadIdx.x == 0) {
        for (int g = NG - 1; g >= 0; g--)
            if (g_gstart[g] < 0) g_gstart[g] = g_gstart[g + 1];
    }
}

// ---------------- tensor-core GEMM: Y[M,128] = X[M,128] @ W[128,128] -------
// bf16 3-pass split (hi/lo) for ~fp32 accuracy. Block = 128 rows, 256 thr.
// smem: Ahi/Alo/Bhi/Blo each 128x128 bf16, 272B pitched rows (conflict-free
// ldmatrix). Epilogue writes fp32 Y + bf16 Ybf.

#define PITCHB 272                 // bytes per pitched row (136 bf16)
#define TILE_BYTES (128 * PITCHB)  // 34816
#define SMEM_GEMM (4 * TILE_BYTES) // 139264

__device__ __forceinline__ void ldsm_x4(uint32_t addr, uint32_t& r0, uint32_t& r1,
                                        uint32_t& r2, uint32_t& r3) {
    asm volatile("ldmatrix.sync.aligned.m8n8.x4.shared.b16 {%0,%1,%2,%3}, [%4];"
                 : "=r"(r0), "=r"(r1), "=r"(r2), "=r"(r3) : "r"(addr));
}
__device__ __forceinline__ void ldsm_x2t(uint32_t addr, uint32_t& r0, uint32_t& r1) {
    asm volatile("ldmatrix.sync.aligned.m8n8.x2.trans.shared.b16 {%0,%1}, [%2];"
                 : "=r"(r0), "=r"(r1) : "r"(addr));
}
__device__ __forceinline__ void mma_bf16(float& c0, float& c1, float& c2, float& c3,
                                         uint32_t a0, uint32_t a1, uint32_t a2, uint32_t a3,
                                         uint32_t b0, uint32_t b1) {
    asm volatile("mma.sync.aligned.m16n8k16.row.col.f32.bf16.bf16.f32 "
                 "{%0,%1,%2,%3},{%4,%5,%6,%7},{%8,%9},{%0,%1,%2,%3};"
                 : "+f"(c0), "+f"(c1), "+f"(c2), "+f"(c3)
                 : "r"(a0), "r"(a1), "r"(a2), "r"(a3), "r"(b0), "r"(b1));
}

__device__ __forceinline__ uint32_t pack2(float x, float y) {
    __nv_bfloat162 h = __floats2bfloat162_rn(x, y);
    return *reinterpret_cast<uint32_t*>(&h);
}
__device__ __forceinline__ uint32_t pack2lo(float x, float y, uint32_t hp) {
    float hx = __uint_as_float((hp & 0xFFFFu) << 16);
    float hy = __uint_as_float(hp & 0xFFFF0000u);
    __nv_bfloat162 h = __floats2bfloat162_rn(x - hx, y - hy);
    return *reinterpret_cast<uint32_t*>(&h);
}

__global__ __launch_bounds__(256, 1) void k_gemm(const float* __restrict__ X,
                                                 const float* __restrict__ W,
                                                 float* __restrict__ Y,
                                                 __nv_bfloat16* __restrict__ Ybf) {
    extern __shared__ char smem[];
    char* sAhi = smem;
    char* sAlo = smem + TILE_BYTES;
    char* sBhi = smem + 2 * TILE_BYTES;
    char* sBlo = smem + 3 * TILE_BYTES;

    int tid = threadIdx.x;
    int base = blockIdx.x * 128;

    // load + split: X tile and W (each 128x128 fp32, float4 per thread-iter)
    for (int it = tid; it < 4096; it += 256) {
        int row = it >> 5;
        int c4 = (it & 31) * 4;
        // X
        {
            int r = min(base + row, NN - 1);
            float4 v = *reinterpret_cast<const float4*>(X + (size_t)r * F + c4);
            uint32_t h0 = pack2(v.x, v.y), h1 = pack2(v.z, v.w);
            uint32_t l0 = pack2lo(v.x, v.y, h0), l1 = pack2lo(v.z, v.w, h1);
            *reinterpret_cast<uint2*>(sAhi + row * PITCHB + c4 * 2) = make_uint2(h0, h1);
            *reinterpret_cast<uint2*>(sAlo + row * PITCHB + c4 * 2) = make_uint2(l0, l1);
        }
        // W
        {
            float4 v = *reinterpret_cast<const float4*>(W + row * F + c4);
            uint32_t h0 = pack2(v.x, v.y), h1 = pack2(v.z, v.w);
            uint32_t l0 = pack2lo(v.x, v.y, h0), l1 = pack2lo(v.z, v.w, h1);
            *reinterpret_cast<uint2*>(sBhi + row * PITCHB + c4 * 2) = make_uint2(h0, h1);
            *reinterpret_cast<uint2*>(sBlo + row * PITCHB + c4 * 2) = make_uint2(l0, l1);
        }
    }
    __syncthreads();

    int lane = tid & 31;
    int w = tid >> 5;
    int m_base = w * 16;

    uint32_t sAhi_u = (uint32_t)__cvta_generic_to_shared(sAhi);
    uint32_t sAlo_u = (uint32_t)__cvta_generic_to_shared(sAlo);
    uint32_t sBhi_u = (uint32_t)__cvta_generic_to_shared(sBhi);
    uint32_t sBlo_u = (uint32_t)__cvta_generic_to_shared(sBlo);

    // A frag address: tile = lane>>3; rows (lane&7) + (tile&1)*8 ; k-halves (tile>>1)*8
    uint32_t aoff = (uint32_t)((m_base + (lane & 7) + ((lane >> 3) & 1) * 8) * PITCHB
                               + ((lane >> 4) * 16));
    // B frag address: rows (k) = lane&15
    uint32_t boff = (uint32_t)((lane & 15) * PITCHB);

    float acc[16][4];
#pragma unroll
    for (int j = 0; j < 16; j++)
#pragma unroll
        for (int q = 0; q < 4; q++) acc[j][q] = 0.0f;

#pragma unroll
    for (int s = 0; s < 8; s++) {
        uint32_t ah0, ah1, ah2, ah3, al0, al1, al2, al3;
        ldsm_x4(sAhi_u + aoff + s * 32, ah0, ah1, ah2, ah3);
        ldsm_x4(sAlo_u + aoff + s * 32, al0, al1, al2, al3);
        uint32_t bbase = boff + s * 16 * PITCHB;
#pragma unroll
        for (int j = 0; j < 16; j++) {
            uint32_t bh0, bh1, bl0, bl1;
            ldsm_x2t(sBhi_u + bbase + j * 16, bh0, bh1);
            mma_bf16(acc[j][0], acc[j][1], acc[j][2], acc[j][3],
                     ah0, ah1, ah2, ah3, bh0, bh1);
            mma_bf16(acc[j][0], acc[j][1], acc[j][2], acc[j][3],
                     al0, al1, al2, al3, bh0, bh1);
            ldsm_x2t(sBlo_u + bbase + j * 16, bl0, bl1);
            mma_bf16(acc[j][0], acc[j][1], acc[j][2], acc[j][3],
                     ah0, ah1, ah2, ah3, bl0, bl1);
        }
    }

    // epilogue: c0,c1 -> (row g, col 2t..2t+1), c2,c3 -> (row g+8)
    int g = lane >> 2;
    int t = lane & 3;
    int r0 = base + m_base + g;
    int r1 = r0 + 8;
#pragma unroll
    for (int j = 0; j < 16; j++) {
        int col = j * 8 + t * 2;
        if (r0 < NN) {
            *reinterpret_cast<float2*>(Y + (size_t)r0 * F + col) =
                make_float2(acc[j][0], acc[j][1]);
            *reinterpret_cast<uint32_t*>(Ybf + (size_t)r0 * F + col) =
                pack2(acc[j][0], acc[j][1]);
        }
        if (r1 < NN) {
            *reinterpret_cast<float2*>(Y + (size_t)r1 * F + col) =
                make_float2(acc[j][2], acc[j][3]);
            *reinterpret_cast<uint32_t*>(Ybf + (size_t)r1 * F + col) =
                pack2(acc[j][2], acc[j][3]);
        }
    }
}

// ---------------- aggregation: H[v] = relu(Y[v] + invdeg*sum_nbr Ybf + b) --
__global__ __launch_bounds__(256) void k_agg(const float* __restrict__ Y,
                                             const __nv_bfloat16* __restrict__ Ybf,
                                             const float* __restrict__ bias,
                                             float* __restrict__ H) {
    int gw   = (blockIdx.x * blockDim.x + threadIdx.x) >> 5;
    int lane = threadIdx.x & 31;
    if (gw >= NN) return;

    int beg = g_rowoff[gw];
    int end = g_rowoff[gw + 1];
    const uint2* __restrict__ Yb2 = reinterpret_cast<const uint2*>(Ybf);

    float ax = 0.f, ay = 0.f, az = 0.f, aw = 0.f;
    int e = beg;
    for (; e + 1 < end; e += 2) {
        int s0 = g_csr[e];
        int s1 = g_csr[e + 1];
        uint2 u0 = Yb2[(size_t)s0 * 32 + lane];
        uint2 u1 = Yb2[(size_t)s1 * 32 + lane];
        ax += __uint_as_float(u0.x << 16)       + __uint_as_float(u1.x << 16);
        ay += __uint_as_float(u0.x & 0xFFFF0000u) + __uint_as_float(u1.x & 0xFFFF0000u);
        az += __uint_as_float(u0.y << 16)       + __uint_as_float(u1.y << 16);
        aw += __uint_as_float(u0.y & 0xFFFF0000u) + __uint_as_float(u1.y & 0xFFFF0000u);
    }
    if (e < end) {
        int s = g_csr[e];
        uint2 u = Yb2[(size_t)s * 32 + lane];
        ax += __uint_as_float(u.x << 16);
        ay += __uint_as_float(u.x & 0xFFFF0000u);
        az += __uint_as_float(u.y << 16);
        aw += __uint_as_float(u.y & 0xFFFF0000u);
    }

    float inv = g_invdeg[gw];
    float4 yv = reinterpret_cast<const float4*>(Y)[(size_t)gw * 32 + lane];
    float4 bb = reinterpret_cast<const float4*>(bias)[lane];
    float4 h;
    h.x = fmaxf(fmaf(ax, inv, yv.x) + bb.x, 0.f);
    h.y = fmaxf(fmaf(ay, inv, yv.y) + bb.y, 0.f);
    h.z = fmaxf(fmaf(az, inv, yv.z) + bb.z, 0.f);
    h.w = fmaxf(fmaf(aw, inv, yv.w) + bb.w, 0.f);
    reinterpret_cast<float4*>(H)[(size_t)gw * 32 + lane] = h;
}

// ---------------- per-graph mean pooling (2-stage, chip-filling) ----------
__global__ void k_pool1(const float* __restrict__ H) {
    int bx = blockIdx.x;            // NG*8 blocks
    int g = bx >> 3, c = bx & 7;
    int tid = threadIdx.x;          // 512
    int col = tid & 127;
    int sub = tid >> 7;             // 0..3
    int s = g_gstart[g];
    int e = g_gstart[g + 1];
    float p = 0.0f;
    for (int r = s + c + 8 * sub; r < e; r += 32) p += H[(size_t)r * F + col];
    __shared__ float sm[512];
    sm[tid] = p;
    __syncthreads();
    if (tid < 128) {
        g_part[bx * F + col] = sm[tid] + sm[tid + 128] + sm[tid + 256] + sm[tid + 384];
    }
}

__global__ void k_pool2(float* __restrict__ out) {
    int g = blockIdx.x;
    int tid = threadIdx.x;          // 128
    float s = 0.f;
#pragma unroll
    for (int c = 0; c < 8; c++) s += g_part[(g * 8 + c) * F + tid];
    int cnt = g_gstart[g + 1] - g_gstart[g];
    float mean = s / (float)max(cnt, 1);
    g_hg[g * F + tid] = mean;
    out[g * F + tid]  = mean;
}

// ---------------- decoder ----------------
__global__ void k_dec(const float* __restrict__ Wd1, const float* __restrict__ bd1,
                      const float* __restrict__ Wd2, const float* __restrict__ bd2,
                      float* __restrict__ out) {
    int g = blockIdx.x;
    int tid = threadIdx.x;          // 128
    __shared__ float hgs[F], ts[F];
    hgs[tid] = g_hg[g * F + tid];
    __syncthreads();
    float s0 = 0.f, s1 = 0.f, s2 = 0.f, s3 = 0.f;
#pragma unroll 8
    for (int k = 0; k < F; k += 4) {
        s0 = fmaf(hgs[k],     Wd1[(k)     * F + tid], s0);
        s1 = fmaf(hgs[k + 1], Wd1[(k + 1) * F + tid], s1);
        s2 = fmaf(hgs[k + 2], Wd1[(k + 2) * F + tid], s2);
        s3 = fmaf(hgs[k + 3], Wd1[(k + 3) * F + tid], s3);
    }
    ts[tid] = fmaxf((s0 + s1) + (s2 + s3) + bd1[tid], 0.f);
    __syncthreads();
    if (tid < OUTF) {
        float o0 = 0.f, o1 = 0.f, o2 = 0.f, o3 = 0.f;
#pragma unroll 8
        for (int k = 0; k < F; k += 4) {
            o0 = fmaf(ts[k],     Wd2[(k)     * OUTF + tid], o0);
            o1 = fmaf(ts[k + 1], Wd2[(k + 1) * OUTF + tid], o1);
            o2 = fmaf(ts[k + 2], Wd2[(k + 2) * OUTF + tid], o2);
            o3 = fmaf(ts[k + 3], Wd2[(k + 3) * OUTF + tid], o3);
        }
        out[NG * F + g * OUTF + tid] = (o0 + o1) + (o2 + o3) + bd2[tid];
    }
}

// ---------------- launch ----------------
extern "C" void kernel_launch(void* const* d_in, const int* in_sizes, int n_in,
                              void* d_out, int out_size) {
    const float* feat = (const float*)d_in[0];
    const int*   src  = (const int*)d_in[1];
    const int*   dst  = (const int*)d_in[2];
    const int*   gid  = (const int*)d_in[3];
    const float* W1   = (const float*)d_in[4];
    const float* b1   = (const float*)d_in[5];
    const float* W2   = (const float*)d_in[6];
    const float* b2   = (const float*)d_in[7];
    const float* Wd1  = (const float*)d_in[8];
    const float* bd1  = (const float*)d_in[9];
    const float* Wd2  = (const float*)d_in[10];
    const float* bd2  = (const float*)d_in[11];
    float* out = (float*)d_out;

    float *buf0, *buf1;
    __nv_bfloat16* bufbf;
    cudaGetSymbolAddress((void**)&buf0, g_buf0);
    cudaGetSymbolAddress((void**)&buf1, g_buf1);
    cudaGetSymbolAddress((void**)&bufbf, g_bufbf);

    cudaFuncSetAttribute(k_gemm, cudaFuncAttributeMaxDynamicSharedMemorySize, SMEM_GEMM);

    // graph structure (identical both layers)
    k_init<<<(NN + 255) / 256, 256>>>();
    k_deg<<<(NE + 255) / 256, 256>>>(dst);
    k_scan<<<1, 1024>>>();
    k_scatter<<<(NE + 255) / 256, 256>>>(src, dst);
    k_gb<<<(NN + 255) / 256, 256>>>(gid);
    k_gfix<<<1, 32>>>();

    int gblocks = (NN + 127) / 128;

    // layer 1
    k_gemm<<<gblocks, 256, SMEM_GEMM>>>(feat, W1, buf0, bufbf);
    k_agg<<<(NN * 32 + 255) / 256, 256>>>(buf0, bufbf, b1, buf1);

    // layer 2
    k_gemm<<<gblocks, 256, SMEM_GEMM>>>(buf1, W2, buf0, bufbf);
    k_agg<<<(NN * 32 + 255) / 256, 256>>>(buf0, bufbf, b2, buf1);

    // pooling + decoder
    k_pool1<<<NG * 8, 512>>>(buf1);
    k_pool2<<<NG, 128>>>(out);
    k_dec<<<NG, 128>>>(Wd1, bd1, Wd2, bd2, out);
}

// round 3
// speedup vs baseline: 2.6552x; 1.6229x over previous
#include <cuda_runtime.h>
#include <cuda_bf16.h>
#include <cstdint>

#define NN 100000
#define NE 1600000
#define F  128
#define NG 64
#define OUTF 64

#define SCAN_BLK 1024
#define SCAN_NB  ((NN + SCAN_BLK - 1) / SCAN_BLK)   // 98

// ---------------- scratch ----------------
__device__ float g_buf0[NN * F];              // Y = X@W (fp32, self term)
__device__ float g_buf1[NN * F];              // layer output H
__device__ __nv_bfloat16 g_bufbf[NN * F];     // bf16 copy of Y for gathers
__device__ int   g_deg[NN];
__device__ int   g_rowoff[NN + 1];
__device__ int   g_cursor[NN];
__device__ int   g_csr[NE];
__device__ float g_invdeg[NN];
__device__ int   g_gstart[NG + 1];
__device__ float g_hg[NG * F];
__device__ float g_part[NG * 8 * F];
__device__ int   g_bsum[SCAN_NB];
__device__ int   g_boff[SCAN_NB];

// ---------------- CSR build ----------------
__global__ void k_init() {
    int i = blockIdx.x * blockDim.x + threadIdx.x;
    if (i < NN) g_deg[i] = 0;
    if (i <= NG) g_gstart[i] = (i == NG) ? NN : -1;
}

// 4 edges per thread, int4 loads (NE % 4 == 0)
__global__ void k_deg(const int* __restrict__ dst) {
    int t = blockIdx.x * blockDim.x + threadIdx.x;
    if (t < NE / 4) {
        int4 d = reinterpret_cast<const int4*>(dst)[t];
        atomicAdd(&g_deg[d.x], 1);
        atomicAdd(&g_deg[d.y], 1);
        atomicAdd(&g_deg[d.z], 1);
        atomicAdd(&g_deg[d.w], 1);
    }
}

// -------- 3-phase multi-block exclusive scan over g_deg --------
__global__ void k_scan_a() {               // 98 blocks x 1024
    __shared__ int sm[SCAN_BLK];
    int tid = threadIdx.x;
    int i = blockIdx.x * SCAN_BLK + tid;
    int v = (i < NN) ? g_deg[i] : 0;
    sm[tid] = v;
    __syncthreads();
    // inclusive scan in smem
    for (int off = 1; off < SCAN_BLK; off <<= 1) {
        int a = (tid >= off) ? sm[tid - off] : 0;
        __syncthreads();
        sm[tid] += a;
        __syncthreads();
    }
    if (i < NN) g_rowoff[i] = sm[tid] - v;     // block-local exclusive
    if (tid == SCAN_BLK - 1) g_bsum[blockIdx.x] = sm[tid];
}

__global__ void k_scan_b() {               // 1 block x 128 (SCAN_NB=98)
    __shared__ int sm[128];
    int tid = threadIdx.x;
    int v = (tid < SCAN_NB) ? g_bsum[tid] : 0;
    sm[tid] = v;
    __syncthreads();
    for (int off = 1; off < 128; off <<= 1) {
        int a = (tid >= off) ? sm[tid - off] : 0;
        __syncthreads();
        sm[tid] += a;
        __syncthreads();
    }
    if (tid < SCAN_NB) g_boff[tid] = sm[tid] - v;
}

__global__ void k_scan_c() {               // 98 blocks x 1024
    int tid = threadIdx.x;
    int i = blockIdx.x * SCAN_BLK + tid;
    if (i < NN) {
        int r = g_rowoff[i] + g_boff[blockIdx.x];
        g_rowoff[i] = r;
        g_cursor[i] = r;
        g_invdeg[i] = 1.0f / (float)max(g_deg[i], 1);
    }
    if (i == 0) g_rowoff[NN] = NE;
}

// 2 edges per thread, int2 loads
__global__ void k_scatter(const int* __restrict__ src, const int* __restrict__ dst) {
    int t = blockIdx.x * blockDim.x + threadIdx.x;
    if (t < NE / 2) {
        int2 d = reinterpret_cast<const int2*>(dst)[t];
        int2 s = reinterpret_cast<const int2*>(src)[t];
        int p0 = atomicAdd(&g_cursor[d.x], 1);
        int p1 = atomicAdd(&g_cursor[d.y], 1);
        g_csr[p0] = s.x;
        g_csr[p1] = s.y;
    }
}

__global__ void k_gb(const int* __restrict__ gid) {
    int i = blockIdx.x * blockDim.x + threadIdx.x;
    if (i < NN) {
        int g = gid[i];
        if (i == 0 || gid[i - 1] != g) g_gstart[g] = i;
    }
}
__global__ void k_gfix() {
    if (threadIdx.x == 0) {
        for (int g = NG - 1; g >= 0; g--)
            if (g_gstart[g] < 0) g_gstart[g] = g_gstart[g + 1];
    }
}

// ---------------- tensor-core GEMM (bf16 3-pass split) ----------------
#define PITCHB 272
#define TILE_BYTES (128 * PITCHB)
#define SMEM_GEMM (4 * TILE_BYTES)

__device__ __forceinline__ void ldsm_x4(uint32_t addr, uint32_t& r0, uint32_t& r1,
                                        uint32_t& r2, uint32_t& r3) {
    asm volatile("ldmatrix.sync.aligned.m8n8.x4.shared.b16 {%0,%1,%2,%3}, [%4];"
                 : "=r"(r0), "=r"(r1), "=r"(r2), "=r"(r3) : "r"(addr));
}
__device__ __forceinline__ void ldsm_x2t(uint32_t addr, uint32_t& r0, uint32_t& r1) {
    asm volatile("ldmatrix.sync.aligned.m8n8.x2.trans.shared.b16 {%0,%1}, [%2];"
                 : "=r"(r0), "=r"(r1) : "r"(addr));
}
__device__ __forceinline__ void mma_bf16(float& c0, float& c1, float& c2, float& c3,
                                         uint32_t a0, uint32_t a1, uint32_t a2, uint32_t a3,
                                         uint32_t b0, uint32_t b1) {
    asm volatile("mma.sync.aligned.m16n8k16.row.col.f32.bf16.bf16.f32 "
                 "{%0,%1,%2,%3},{%4,%5,%6,%7},{%8,%9},{%0,%1,%2,%3};"
                 : "+f"(c0), "+f"(c1), "+f"(c2), "+f"(c3)
                 : "r"(a0), "r"(a1), "r"(a2), "r"(a3), "r"(b0), "r"(b1));
}
__device__ __forceinline__ uint32_t pack2(float x, float y) {
    __nv_bfloat162 h = __floats2bfloat162_rn(x, y);
    return *reinterpret_cast<uint32_t*>(&h);
}
__device__ __forceinline__ uint32_t pack2lo(float x, float y, uint32_t hp) {
    float hx = __uint_as_float((hp & 0xFFFFu) << 16);
    float hy = __uint_as_float(hp & 0xFFFF0000u);
    __nv_bfloat162 h = __floats2bfloat162_rn(x - hx, y - hy);
    return *reinterpret_cast<uint32_t*>(&h);
}

__global__ __launch_bounds__(256, 1) void k_gemm(const float* __restrict__ X,
                                                 const float* __restrict__ W,
                                                 float* __restrict__ Y,
                                                 __nv_bfloat16* __restrict__ Ybf) {
    extern __shared__ char smem[];
    char* sAhi = smem;
    char* sAlo = smem + TILE_BYTES;
    char* sBhi = smem + 2 * TILE_BYTES;
    char* sBlo = smem + 3 * TILE_BYTES;

    int tid = threadIdx.x;
    int base = blockIdx.x * 128;

    for (int it = tid; it < 4096; it += 256) {
        int row = it >> 5;
        int c4 = (it & 31) * 4;
        {
            int r = min(base + row, NN - 1);
            float4 v = *reinterpret_cast<const float4*>(X + (size_t)r * F + c4);
            uint32_t h0 = pack2(v.x, v.y), h1 = pack2(v.z, v.w);
            uint32_t l0 = pack2lo(v.x, v.y, h0), l1 = pack2lo(v.z, v.w, h1);
            *reinterpret_cast<uint2*>(sAhi + row * PITCHB + c4 * 2) = make_uint2(h0, h1);
            *reinterpret_cast<uint2*>(sAlo + row * PITCHB + c4 * 2) = make_uint2(l0, l1);
        }
        {
            float4 v = *reinterpret_cast<const float4*>(W + row * F + c4);
            uint32_t h0 = pack2(v.x, v.y), h1 = pack2(v.z, v.w);
            uint32_t l0 = pack2lo(v.x, v.y, h0), l1 = pack2lo(v.z, v.w, h1);
            *reinterpret_cast<uint2*>(sBhi + row * PITCHB + c4 * 2) = make_uint2(h0, h1);
            *reinterpret_cast<uint2*>(sBlo + row * PITCHB + c4 * 2) = make_uint2(l0, l1);
        }
    }
    __syncthreads();

    int lane = tid & 31;
    int w = tid >> 5;
    int m_base = w * 16;

    uint32_t sAhi_u = (uint32_t)__cvta_generic_to_shared(sAhi);
    uint32_t sAlo_u = (uint32_t)__cvta_generic_to_shared(sAlo);
    uint32_t sBhi_u = (uint32_t)__cvta_generic_to_shared(sBhi);
    uint32_t sBlo_u = (uint32_t)__cvta_generic_to_shared(sBlo);

    uint32_t aoff = (uint32_t)((m_base + (lane & 7) + ((lane >> 3) & 1) * 8) * PITCHB
                               + ((lane >> 4) * 16));
    uint32_t boff = (uint32_t)((lane & 15) * PITCHB);

    float acc[16][4];
#pragma unroll
    for (int j = 0; j < 16; j++)
#pragma unroll
        for (int q = 0; q < 4; q++) acc[j][q] = 0.0f;

#pragma unroll
    for (int s = 0; s < 8; s++) {
        uint32_t ah0, ah1, ah2, ah3, al0, al1, al2, al3;
        ldsm_x4(sAhi_u + aoff + s * 32, ah0, ah1, ah2, ah3);
        ldsm_x4(sAlo_u + aoff + s * 32, al0, al1, al2, al3);
        uint32_t bbase = boff + s * 16 * PITCHB;
#pragma unroll
        for (int j = 0; j < 16; j++) {
            uint32_t bh0, bh1, bl0, bl1;
            ldsm_x2t(sBhi_u + bbase + j * 16, bh0, bh1);
            mma_bf16(acc[j][0], acc[j][1], acc[j][2], acc[j][3],
                     ah0, ah1, ah2, ah3, bh0, bh1);
            mma_bf16(acc[j][0], acc[j][1], acc[j][2], acc[j][3],
                     al0, al1, al2, al3, bh0, bh1);
            ldsm_x2t(sBlo_u + bbase + j * 16, bl0, bl1);
            mma_bf16(acc[j][0], acc[j][1], acc[j][2], acc[j][3],
                     ah0, ah1, ah2, ah3, bl0, bl1);
        }
    }

    int g = lane >> 2;
    int t = lane & 3;
    int r0 = base + m_base + g;
    int r1 = r0 + 8;
#pragma unroll
    for (int j = 0; j < 16; j++) {
        int col = j * 8 + t * 2;
        if (r0 < NN) {
            *reinterpret_cast<float2*>(Y + (size_t)r0 * F + col) =
                make_float2(acc[j][0], acc[j][1]);
            *reinterpret_cast<uint32_t*>(Ybf + (size_t)r0 * F + col) =
                pack2(acc[j][0], acc[j][1]);
        }
        if (r1 < NN) {
            *reinterpret_cast<float2*>(Y + (size_t)r1 * F + col) =
                make_float2(acc[j][2], acc[j][3]);
            *reinterpret_cast<uint32_t*>(Ybf + (size_t)r1 * F + col) =
                pack2(acc[j][2], acc[j][3]);
        }
    }
}

// ---------------- aggregation: H[v] = relu(Y[v] + invdeg*sum_nbr Ybf + b) --
// warp/node, unroll-4 gathers (MLP>=4) to hide L2 latency.
__device__ __forceinline__ void acc_bf2(float& ax, float& ay, float& az, float& aw,
                                        uint2 u) {
    ax += __uint_as_float(u.x << 16);
    ay += __uint_as_float(u.x & 0xFFFF0000u);
    az += __uint_as_float(u.y << 16);
    aw += __uint_as_float(u.y & 0xFFFF0000u);
}

__global__ __launch_bounds__(256) void k_agg(const float* __restrict__ Y,
                                             const __nv_bfloat16* __restrict__ Ybf,
                                             const float* __restrict__ bias,
                                             float* __restrict__ H) {
    int gw   = (blockIdx.x * blockDim.x + threadIdx.x) >> 5;
    int lane = threadIdx.x & 31;
    if (gw >= NN) return;

    int beg = g_rowoff[gw];
    int end = g_rowoff[gw + 1];
    const uint2* __restrict__ Yb2 = reinterpret_cast<const uint2*>(Ybf);

    float ax = 0.f, ay = 0.f, az = 0.f, aw = 0.f;
    int e = beg;
    for (; e + 3 < end; e += 4) {
        int s0 = g_csr[e];
        int s1 = g_csr[e + 1];
        int s2 = g_csr[e + 2];
        int s3 = g_csr[e + 3];
        uint2 u0 = Yb2[(size_t)s0 * 32 + lane];
        uint2 u1 = Yb2[(size_t)s1 * 32 + lane];
        uint2 u2 = Yb2[(size_t)s2 * 32 + lane];
        uint2 u3 = Yb2[(size_t)s3 * 32 + lane];
        acc_bf2(ax, ay, az, aw, u0);
        acc_bf2(ax, ay, az, aw, u1);
        acc_bf2(ax, ay, az, aw, u2);
        acc_bf2(ax, ay, az, aw, u3);
    }
    for (; e < end; e++) {
        int s = g_csr[e];
        uint2 u = Yb2[(size_t)s * 32 + lane];
        acc_bf2(ax, ay, az, aw, u);
    }

    float inv = g_invdeg[gw];
    float4 yv = reinterpret_cast<const float4*>(Y)[(size_t)gw * 32 + lane];
    float4 bb = reinterpret_cast<const float4*>(bias)[lane];
    float4 h;
    h.x = fmaxf(fmaf(ax, inv, yv.x) + bb.x, 0.f);
    h.y = fmaxf(fmaf(ay, inv, yv.y) + bb.y, 0.f);
    h.z = fmaxf(fmaf(az, inv, yv.z) + bb.z, 0.f);
    h.w = fmaxf(fmaf(aw, inv, yv.w) + bb.w, 0.f);
    reinterpret_cast<float4*>(H)[(size_t)gw * 32 + lane] = h;
}

// ---------------- per-graph mean pooling (2-stage) ----------
__global__ void k_pool1(const float* __restrict__ H) {
    int bx = blockIdx.x;
    int g = bx >> 3, c = bx & 7;
    int tid = threadIdx.x;
    int col = tid & 127;
    int sub = tid >> 7;
    int s = g_gstart[g];
    int e = g_gstart[g + 1];
    float p = 0.0f;
    for (int r = s + c + 8 * sub; r < e; r += 32) p += H[(size_t)r * F + col];
    __shared__ float sm[512];
    sm[tid] = p;
    __syncthreads();
    if (tid < 128) {
        g_part[bx * F + col] = sm[tid] + sm[tid + 128] + sm[tid + 256] + sm[tid + 384];
    }
}

__global__ void k_pool2(float* __restrict__ out) {
    int g = blockIdx.x;
    int tid = threadIdx.x;
    float s = 0.f;
#pragma unroll
    for (int c = 0; c < 8; c++) s += g_part[(g * 8 + c) * F + tid];
    int cnt = g_gstart[g + 1] - g_gstart[g];
    float mean = s / (float)max(cnt, 1);
    g_hg[g * F + tid] = mean;
    out[g * F + tid]  = mean;
}

// ---------------- decoder ----------------
__global__ void k_dec(const float* __restrict__ Wd1, const float* __restrict__ bd1,
                      const float* __restrict__ Wd2, const float* __restrict__ bd2,
                      float* __restrict__ out) {
    int g = blockIdx.x;
    int tid = threadIdx.x;
    __shared__ float hgs[F], ts[F];
    hgs[tid] = g_hg[g * F + tid];
    __syncthreads();
    float s0 = 0.f, s1 = 0.f, s2 = 0.f, s3 = 0.f;
#pragma unroll 8
    for (int k = 0; k < F; k += 4) {
        s0 = fmaf(hgs[k],     Wd1[(k)     * F + tid], s0);
        s1 = fmaf(hgs[k + 1], Wd1[(k + 1) * F + tid], s1);
        s2 = fmaf(hgs[k + 2], Wd1[(k + 2) * F + tid], s2);
        s3 = fmaf(hgs[k + 3], Wd1[(k + 3) * F + tid], s3);
    }
    ts[tid] = fmaxf((s0 + s1) + (s2 + s3) + bd1[tid], 0.f);
    __syncthreads();
    if (tid < OUTF) {
        float o0 = 0.f, o1 = 0.f, o2 = 0.f, o3 = 0.f;
#pragma unroll 8
        for (int k = 0; k < F; k += 4) {
            o0 = fmaf(ts[k],     Wd2[(k)     * OUTF + tid], o0);
            o1 = fmaf(ts[k + 1], Wd2[(k + 1) * OUTF + tid], o1);
            o2 = fmaf(ts[k + 2], Wd2[(k + 2) * OUTF + tid], o2);
            o3 = fmaf(ts[k + 3], Wd2[(k + 3) * OUTF + tid], o3);
        }
        out[NG * F + g * OUTF + tid] = (o0 + o1) + (o2 + o3) + bd2[tid];
    }
}

// ---------------- launch ----------------
extern "C" void kernel_launch(void* const* d_in, const int* in_sizes, int n_in,
                              void* d_out, int out_size) {
    const float* feat = (const float*)d_in[0];
    const int*   src  = (const int*)d_in[1];
    const int*   dst  = (const int*)d_in[2];
    const int*   gid  = (const int*)d_in[3];
    const float* W1   = (const float*)d_in[4];
    const float* b1   = (const float*)d_in[5];
    const float* W2   = (const float*)d_in[6];
    const float* b2   = (const float*)d_in[7];
    const float* Wd1  = (const float*)d_in[8];
    const float* bd1  = (const float*)d_in[9];
    const float* Wd2  = (const float*)d_in[10];
    const float* bd2  = (const float*)d_in[11];
    float* out = (float*)d_out;

    float *buf0, *buf1;
    __nv_bfloat16* bufbf;
    cudaGetSymbolAddress((void**)&buf0, g_buf0);
    cudaGetSymbolAddress((void**)&buf1, g_buf1);
    cudaGetSymbolAddress((void**)&bufbf, g_bufbf);

    cudaFuncSetAttribute(k_gemm, cudaFuncAttributeMaxDynamicSharedMemorySize, SMEM_GEMM);

    // graph structure (shared by both layers)
    k_init<<<(NN + 255) / 256, 256>>>();
    k_deg<<<(NE / 4 + 255) / 256, 256>>>(dst);
    k_scan_a<<<SCAN_NB, SCAN_BLK>>>();
    k_scan_b<<<1, 128>>>();
    k_scan_c<<<SCAN_NB, SCAN_BLK>>>();
    k_scatter<<<(NE / 2 + 255) / 256, 256>>>(src, dst);
    k_gb<<<(NN + 255) / 256, 256>>>(gid);
    k_gfix<<<1, 32>>>();

    int gblocks = (NN + 127) / 128;

    // layer 1
    k_gemm<<<gblocks, 256, SMEM_GEMM>>>(feat, W1, buf0, bufbf);
    k_agg<<<(NN * 32 + 255) / 256, 256>>>(buf0, bufbf, b1, buf1);

    // layer 2
    k_gemm<<<gblocks, 256, SMEM_GEMM>>>(buf1, W2, buf0, bufbf);
    k_agg<<<(NN * 32 + 255) / 256, 256>>>(buf0, bufbf, b2, buf1);

    // pooling + decoder
    k_pool1<<<NG * 8, 512>>>(buf1);
    k_pool2<<<NG, 128>>>(out);
    k_dec<<<NG, 128>>>(Wd1, bd1, Wd2, bd2, out);
}

// round 4
// speedup vs baseline: 3.8679x; 1.4567x over previous
#include <cuda_runtime.h>
#include <cuda_bf16.h>
#include <cstdint>

#define NN 100000
#define NE 1600000
#define F  128
#define NG 64
#define OUTF 64

#define SCAN_BLK 1024
#define SCAN_NB  ((NN + SCAN_BLK - 1) / SCAN_BLK)   // 98

// ---------------- scratch ----------------
__device__ __nv_bfloat16 g_ybf[NN * F];       // Y = X@W (bf16)
__device__ __nv_bfloat16 g_hbf[NN * F];       // layer output H (bf16)
__device__ int   g_deg[NN];
__device__ int   g_rowoff[NN + 1];
__device__ int   g_cursor[NN];
__device__ int   g_csr[NE];
__device__ float g_invdeg[NN];
__device__ int   g_gstart[NG + 1];
__device__ float g_hg[NG * F];
__device__ float g_part[NG * 8 * F];
__device__ int   g_bsum[SCAN_NB];
__device__ int   g_boff[SCAN_NB];

// ---------------- CSR build ----------------
__global__ void k_init() {
    int i = blockIdx.x * blockDim.x + threadIdx.x;
    if (i < NN) g_deg[i] = 0;
}

__global__ void k_deg(const int* __restrict__ dst) {
    int t = blockIdx.x * blockDim.x + threadIdx.x;
    if (t < NE / 4) {
        int4 d = reinterpret_cast<const int4*>(dst)[t];
        atomicAdd(&g_deg[d.x], 1);
        atomicAdd(&g_deg[d.y], 1);
        atomicAdd(&g_deg[d.z], 1);
        atomicAdd(&g_deg[d.w], 1);
    }
}

__global__ void k_scan_a() {
    __shared__ int sm[SCAN_BLK];
    int tid = threadIdx.x;
    int i = blockIdx.x * SCAN_BLK + tid;
    int v = (i < NN) ? g_deg[i] : 0;
    sm[tid] = v;
    __syncthreads();
    for (int off = 1; off < SCAN_BLK; off <<= 1) {
        int a = (tid >= off) ? sm[tid - off] : 0;
        __syncthreads();
        sm[tid] += a;
        __syncthreads();
    }
    if (i < NN) g_rowoff[i] = sm[tid] - v;
    if (tid == SCAN_BLK - 1) g_bsum[blockIdx.x] = sm[tid];
}

// block-partial scan + per-graph boundaries via binary search (gid sorted)
__global__ void k_scan_b(const int* __restrict__ gid) {
    __shared__ int sm[128];
    int tid = threadIdx.x;
    int v = (tid < SCAN_NB) ? g_bsum[tid] : 0;
    sm[tid] = v;
    __syncthreads();
    for (int off = 1; off < 128; off <<= 1) {
        int a = (tid >= off) ? sm[tid - off] : 0;
        __syncthreads();
        sm[tid] += a;
        __syncthreads();
    }
    if (tid < SCAN_NB) g_boff[tid] = sm[tid] - v;
    if (tid <= NG) {
        if (tid == NG) {
            g_gstart[NG] = NN;
        } else {
            int lo = 0, hi = NN;
            while (lo < hi) {
                int m = (lo + hi) >> 1;
                if (gid[m] < tid) lo = m + 1; else hi = m;
            }
            g_gstart[tid] = lo;
        }
    }
}

__global__ void k_scan_c() {
    int tid = threadIdx.x;
    int i = blockIdx.x * SCAN_BLK + tid;
    if (i < NN) {
        int r = g_rowoff[i] + g_boff[blockIdx.x];
        g_rowoff[i] = r;
        g_cursor[i] = r;
        g_invdeg[i] = 1.0f / (float)max(g_deg[i], 1);
    }
    if (i == 0) g_rowoff[NN] = NE;
}

__global__ void k_scatter(const int* __restrict__ src, const int* __restrict__ dst) {
    int t = blockIdx.x * blockDim.x + threadIdx.x;
    if (t < NE / 4) {
        int4 d = reinterpret_cast<const int4*>(dst)[t];
        int4 s = reinterpret_cast<const int4*>(src)[t];
        int p0 = atomicAdd(&g_cursor[d.x], 1);
        int p1 = atomicAdd(&g_cursor[d.y], 1);
        int p2 = atomicAdd(&g_cursor[d.z], 1);
        int p3 = atomicAdd(&g_cursor[d.w], 1);
        g_csr[p0] = s.x;
        g_csr[p1] = s.y;
        g_csr[p2] = s.z;
        g_csr[p3] = s.w;
    }
}

// ---------------- tensor-core GEMM: Ybf = bf16( X @ W ) ----------------
// A = bf16(X) single precision pass; B = W split hi+lo (weight precision is
// systematic and survives pooling, X rounding is random and averages out).
#define PITCHB 272
#define TILE_BYTES (128 * PITCHB)
#define SMEM_GEMM (3 * TILE_BYTES)        // sA, sBhi, sBlo

__device__ __forceinline__ void ldsm_x4(uint32_t addr, uint32_t& r0, uint32_t& r1,
                                        uint32_t& r2, uint32_t& r3) {
    asm volatile("ldmatrix.sync.aligned.m8n8.x4.shared.b16 {%0,%1,%2,%3}, [%4];"
                 : "=r"(r0), "=r"(r1), "=r"(r2), "=r"(r3) : "r"(addr));
}
__device__ __forceinline__ void ldsm_x2t(uint32_t addr, uint32_t& r0, uint32_t& r1) {
    asm volatile("ldmatrix.sync.aligned.m8n8.x2.trans.shared.b16 {%0,%1}, [%2];"
                 : "=r"(r0), "=r"(r1) : "r"(addr));
}
__device__ __forceinline__ void mma_bf16(float& c0, float& c1, float& c2, float& c3,
                                         uint32_t a0, uint32_t a1, uint32_t a2, uint32_t a3,
                                         uint32_t b0, uint32_t b1) {
    asm volatile("mma.sync.aligned.m16n8k16.row.col.f32.bf16.bf16.f32 "
                 "{%0,%1,%2,%3},{%4,%5,%6,%7},{%8,%9},{%0,%1,%2,%3};"
                 : "+f"(c0), "+f"(c1), "+f"(c2), "+f"(c3)
                 : "r"(a0), "r"(a1), "r"(a2), "r"(a3), "r"(b0), "r"(b1));
}
__device__ __forceinline__ uint32_t pack2(float x, float y) {
    __nv_bfloat162 h = __floats2bfloat162_rn(x, y);
    return *reinterpret_cast<uint32_t*>(&h);
}
__device__ __forceinline__ uint32_t pack2lo(float x, float y, uint32_t hp) {
    float hx = __uint_as_float((hp & 0xFFFFu) << 16);
    float hy = __uint_as_float(hp & 0xFFFF0000u);
    __nv_bfloat162 h = __floats2bfloat162_rn(x - hx, y - hy);
    return *reinterpret_cast<uint32_t*>(&h);
}

__global__ __launch_bounds__(256, 1) void k_gemm(const float* __restrict__ Xf,
                                                 const __nv_bfloat16* __restrict__ Xb,
                                                 const float* __restrict__ W,
                                                 __nv_bfloat16* __restrict__ Ybf) {
    extern __shared__ char smem[];
    char* sA   = smem;
    char* sBhi = smem + TILE_BYTES;
    char* sBlo = smem + 2 * TILE_BYTES;

    int tid = threadIdx.x;
    int base = blockIdx.x * 128;

    for (int it = tid; it < 4096; it += 256) {
        int row = it >> 5;
        int c4 = (it & 31) * 4;
        // A tile (bf16 only)
        {
            int r = min(base + row, NN - 1);
            uint2 a;
            if (Xb) {
                a = reinterpret_cast<const uint2*>(Xb)[(size_t)r * 32 + (c4 >> 2)];
            } else {
                float4 v = *reinterpret_cast<const float4*>(Xf + (size_t)r * F + c4);
                a = make_uint2(pack2(v.x, v.y), pack2(v.z, v.w));
            }
            *reinterpret_cast<uint2*>(sA + row * PITCHB + c4 * 2) = a;
        }
        // W tile (hi + lo)
        {
            float4 v = *reinterpret_cast<const float4*>(W + row * F + c4);
            uint32_t h0 = pack2(v.x, v.y), h1 = pack2(v.z, v.w);
            uint32_t l0 = pack2lo(v.x, v.y, h0), l1 = pack2lo(v.z, v.w, h1);
            *reinterpret_cast<uint2*>(sBhi + row * PITCHB + c4 * 2) = make_uint2(h0, h1);
            *reinterpret_cast<uint2*>(sBlo + row * PITCHB + c4 * 2) = make_uint2(l0, l1);
        }
    }
    __syncthreads();

    int lane = tid & 31;
    int w = tid >> 5;
    int m_base = w * 16;

    uint32_t sA_u   = (uint32_t)__cvta_generic_to_shared(sA);
    uint32_t sBhi_u = (uint32_t)__cvta_generic_to_shared(sBhi);
    uint32_t sBlo_u = (uint32_t)__cvta_generic_to_shared(sBlo);

    uint32_t aoff = (uint32_t)((m_base + (lane & 7) + ((lane >> 3) & 1) * 8) * PITCHB
                               + ((lane >> 4) * 16));
    uint32_t boff = (uint32_t)((lane & 15) * PITCHB);

    float acc[16][4];
#pragma unroll
    for (int j = 0; j < 16; j++)
#pragma unroll
        for (int q = 0; q < 4; q++) acc[j][q] = 0.0f;

#pragma unroll
    for (int s = 0; s < 8; s++) {
        uint32_t a0, a1, a2, a3;
        ldsm_x4(sA_u + aoff + s * 32, a0, a1, a2, a3);
        uint32_t bbase = boff + s * 16 * PITCHB;
#pragma unroll
        for (int j = 0; j < 16; j++) {
            uint32_t bh0, bh1, bl0, bl1;
            ldsm_x2t(sBhi_u + bbase + j * 16, bh0, bh1);
            mma_bf16(acc[j][0], acc[j][1], acc[j][2], acc[j][3],
                     a0, a1, a2, a3, bh0, bh1);
            ldsm_x2t(sBlo_u + bbase + j * 16, bl0, bl1);
            mma_bf16(acc[j][0], acc[j][1], acc[j][2], acc[j][3],
                     a0, a1, a2, a3, bl0, bl1);
        }
    }

    int g = lane >> 2;
    int t = lane & 3;
    int r0 = base + m_base + g;
    int r1 = r0 + 8;
#pragma unroll
    for (int j = 0; j < 16; j++) {
        int col = j * 8 + t * 2;
        if (r0 < NN)
            *reinterpret_cast<uint32_t*>(Ybf + (size_t)r0 * F + col) =
                pack2(acc[j][0], acc[j][1]);
        if (r1 < NN)
            *reinterpret_cast<uint32_t*>(Ybf + (size_t)r1 * F + col) =
                pack2(acc[j][2], acc[j][3]);
    }
}

// ---------------- aggregation: Hbf[v] = relu(Ybf[v] + invdeg*sum_nbr + b) --
__device__ __forceinline__ void acc_bf2(float& ax, float& ay, float& az, float& aw,
                                        uint2 u) {
    ax += __uint_as_float(u.x << 16);
    ay += __uint_as_float(u.x & 0xFFFF0000u);
    az += __uint_as_float(u.y << 16);
    aw += __uint_as_float(u.y & 0xFFFF0000u);
}

__global__ __launch_bounds__(256) void k_agg(const __nv_bfloat16* __restrict__ Ybf,
                                             const float* __restrict__ bias,
                                             __nv_bfloat16* __restrict__ Hbf) {
    int gw   = (blockIdx.x * blockDim.x + threadIdx.x) >> 5;
    int lane = threadIdx.x & 31;
    if (gw >= NN) return;

    int beg = g_rowoff[gw];
    int end = g_rowoff[gw + 1];
    const uint2* __restrict__ Yb2 = reinterpret_cast<const uint2*>(Ybf);

    float ax = 0.f, ay = 0.f, az = 0.f, aw = 0.f;
    int e = beg;
    for (; e + 7 < end; e += 8) {
        int s0 = g_csr[e],     s1 = g_csr[e + 1], s2 = g_csr[e + 2], s3 = g_csr[e + 3];
        int s4 = g_csr[e + 4], s5 = g_csr[e + 5], s6 = g_csr[e + 6], s7 = g_csr[e + 7];
        uint2 u0 = Yb2[(size_t)s0 * 32 + lane];
        uint2 u1 = Yb2[(size_t)s1 * 32 + lane];
        uint2 u2 = Yb2[(size_t)s2 * 32 + lane];
        uint2 u3 = Yb2[(size_t)s3 * 32 + lane];
        uint2 u4 = Yb2[(size_t)s4 * 32 + lane];
        uint2 u5 = Yb2[(size_t)s5 * 32 + lane];
        uint2 u6 = Yb2[(size_t)s6 * 32 + lane];
        uint2 u7 = Yb2[(size_t)s7 * 32 + lane];
        acc_bf2(ax, ay, az, aw, u0);
        acc_bf2(ax, ay, az, aw, u1);
        acc_bf2(ax, ay, az, aw, u2);
        acc_bf2(ax, ay, az, aw, u3);
        acc_bf2(ax, ay, az, aw, u4);
        acc_bf2(ax, ay, az, aw, u5);
        acc_bf2(ax, ay, az, aw, u6);
        acc_bf2(ax, ay, az, aw, u7);
    }
    for (; e + 3 < end; e += 4) {
        int s0 = g_csr[e], s1 = g_csr[e + 1], s2 = g_csr[e + 2], s3 = g_csr[e + 3];
        uint2 u0 = Yb2[(size_t)s0 * 32 + lane];
        uint2 u1 = Yb2[(size_t)s1 * 32 + lane];
        uint2 u2 = Yb2[(size_t)s2 * 32 + lane];
        uint2 u3 = Yb2[(size_t)s3 * 32 + lane];
        acc_bf2(ax, ay, az, aw, u0);
        acc_bf2(ax, ay, az, aw, u1);
        acc_bf2(ax, ay, az, aw, u2);
        acc_bf2(ax, ay, az, aw, u3);
    }
    for (; e < end; e++) {
        uint2 u = Yb2[(size_t)g_csr[e] * 32 + lane];
        acc_bf2(ax, ay, az, aw, u);
    }

    float inv = g_invdeg[gw];
    uint2 us = Yb2[(size_t)gw * 32 + lane];
    float sx = __uint_as_float(us.x << 16);
    float sy = __uint_as_float(us.x & 0xFFFF0000u);
    float sz = __uint_as_float(us.y << 16);
    float sw = __uint_as_float(us.y & 0xFFFF0000u);
    float4 bb = reinterpret_cast<const float4*>(bias)[lane];
    float hx = fmaxf(fmaf(ax, inv, sx) + bb.x, 0.f);
    float hy = fmaxf(fmaf(ay, inv, sy) + bb.y, 0.f);
    float hz = fmaxf(fmaf(az, inv, sz) + bb.z, 0.f);
    float hw = fmaxf(fmaf(aw, inv, sw) + bb.w, 0.f);
    reinterpret_cast<uint2*>(Hbf)[(size_t)gw * 32 + lane] =
        make_uint2(pack2(hx, hy), pack2(hz, hw));
}

// ---------------- per-graph mean pooling (bf16 input, 2-stage) ----------
__global__ void k_pool1(const __nv_bfloat16* __restrict__ H) {
    int bx = blockIdx.x;            // NG*8 blocks
    int g = bx >> 3, c = bx & 7;
    int tid = threadIdx.x;          // 512
    int col2 = tid & 63;            // uint (2 cols) index
    int sub = tid >> 6;             // 0..7
    int s = g_gstart[g];
    int e = g_gstart[g + 1];
    const uint32_t* __restrict__ H2 = reinterpret_cast<const uint32_t*>(H);
    float px = 0.f, py = 0.f;
    for (int r = s + c * 8 + sub; r < e; r += 64) {
        uint32_t u = H2[(size_t)r * 64 + col2];
        px += __uint_as_float(u << 16);
        py += __uint_as_float(u & 0xFFFF0000u);
    }
    __shared__ float smx[512], smy[512];
    smx[tid] = px;
    smy[tid] = py;
    __syncthreads();
    if (tid < 64) {
        float sx = 0.f, sy = 0.f;
#pragma unroll
        for (int k = 0; k < 8; k++) {
            sx += smx[k * 64 + tid];
            sy += smy[k * 64 + tid];
        }
        *reinterpret_cast<float2*>(&g_part[bx * F + tid * 2]) = make_float2(sx, sy);
    }
}

__global__ void k_pool2(float* __restrict__ out) {
    int g = blockIdx.x;
    int tid = threadIdx.x;          // 128
    float s = 0.f;
#pragma unroll
    for (int c = 0; c < 8; c++) s += g_part[(g * 8 + c) * F + tid];
    int cnt = g_gstart[g + 1] - g_gstart[g];
    float mean = s / (float)max(cnt, 1);
    g_hg[g * F + tid] = mean;
    out[g * F + tid]  = mean;
}

// ---------------- decoder ----------------
__global__ void k_dec(const float* __restrict__ Wd1, const float* __restrict__ bd1,
                      const float* __restrict__ Wd2, const float* __restrict__ bd2,
                      float* __restrict__ out) {
    int g = blockIdx.x;
    int tid = threadIdx.x;          // 128
    __shared__ float hgs[F], ts[F];
    hgs[tid] = g_hg[g * F + tid];
    __syncthreads();
    float s0 = 0.f, s1 = 0.f, s2 = 0.f, s3 = 0.f;
#pragma unroll 8
    for (int k = 0; k < F; k += 4) {
        s0 = fmaf(hgs[k],     Wd1[(k)     * F + tid], s0);
        s1 = fmaf(hgs[k + 1], Wd1[(k + 1) * F + tid], s1);
        s2 = fmaf(hgs[k + 2], Wd1[(k + 2) * F + tid], s2);
        s3 = fmaf(hgs[k + 3], Wd1[(k + 3) * F + tid], s3);
    }
    ts[tid] = fmaxf((s0 + s1) + (s2 + s3) + bd1[tid], 0.f);
    __syncthreads();
    if (tid < OUTF) {
        float o0 = 0.f, o1 = 0.f, o2 = 0.f, o3 = 0.f;
#pragma unroll 8
        for (int k = 0; k < F; k += 4) {
            o0 = fmaf(ts[k],     Wd2[(k)     * OUTF + tid], o0);
            o1 = fmaf(ts[k + 1], Wd2[(k + 1) * OUTF + tid], o1);
            o2 = fmaf(ts[k + 2], Wd2[(k + 2) * OUTF + tid], o2);
            o3 = fmaf(ts[k + 3], Wd2[(k + 3) * OUTF + tid], o3);
        }
        out[NG * F + g * OUTF + tid] = (o0 + o1) + (o2 + o3) + bd2[tid];
    }
}

// ---------------- launch ----------------
extern "C" void kernel_launch(void* const* d_in, const int* in_sizes, int n_in,
                              void* d_out, int out_size) {
    const float* feat = (const float*)d_in[0];
    const int*   src  = (const int*)d_in[1];
    const int*   dst  = (const int*)d_in[2];
    const int*   gid  = (const int*)d_in[3];
    const float* W1   = (const float*)d_in[4];
    const float* b1   = (const float*)d_in[5];
    const float* W2   = (const float*)d_in[6];
    const float* b2   = (const float*)d_in[7];
    const float* Wd1  = (const float*)d_in[8];
    const float* bd1  = (const float*)d_in[9];
    const float* Wd2  = (const float*)d_in[10];
    const float* bd2  = (const float*)d_in[11];
    float* out = (float*)d_out;

    __nv_bfloat16 *ybf, *hbf;
    cudaGetSymbolAddress((void**)&ybf, g_ybf);
    cudaGetSymbolAddress((void**)&hbf, g_hbf);

    cudaFuncSetAttribute(k_gemm, cudaFuncAttributeMaxDynamicSharedMemorySize, SMEM_GEMM);

    // graph structure (shared by both layers)
    k_init<<<(NN + 255) / 256, 256>>>();
    k_deg<<<(NE / 4 + 255) / 256, 256>>>(dst);
    k_scan_a<<<SCAN_NB, SCAN_BLK>>>();
    k_scan_b<<<1, 128>>>(gid);
    k_scan_c<<<SCAN_NB, SCAN_BLK>>>();
    k_scatter<<<(NE / 4 + 255) / 256, 256>>>(src, dst);

    int gblocks = (NN + 127) / 128;

    // layer 1
    k_gemm<<<gblocks, 256, SMEM_GEMM>>>(feat, nullptr, W1, ybf);
    k_agg<<<(NN * 32 + 255) / 256, 256>>>(ybf, b1, hbf);

    // layer 2
    k_gemm<<<gblocks, 256, SMEM_GEMM>>>(nullptr, hbf, W2, ybf);
    k_agg<<<(NN * 32 + 255) / 256, 256>>>(ybf, b2, hbf);

    // pooling + decoder
    k_pool1<<<NG * 8, 512>>>(hbf);
    k_pool2<<<NG, 128>>>(out);
    k_dec<<<NG, 128>>>(Wd1, bd1, Wd2, bd2, out);
}

// round 5
// speedup vs baseline: 3.9882x; 1.0311x over previous
#include <cuda_runtime.h>
#include <cuda_bf16.h>
#include <cstdint>

#define NN 100000
#define NE 1600000
#define F  128
#define NG 64
#define OUTF 64

#define SCAN_BLK 1024
#define SCAN_NB  ((NN + SCAN_BLK - 1) / SCAN_BLK)   // 98

// ---------------- scratch ----------------
__device__ __nv_bfloat16 g_ybf[NN * F];       // Y = X@W (bf16)
__device__ __nv_bfloat16 g_hbf[NN * F];       // layer output H (bf16)
__device__ int   g_deg[NN];
__device__ int   g_rowoff[NN + 1];
__device__ int   g_cursor[NN];
__device__ int   g_csr[NE];
__device__ float g_invdeg[NN];
__device__ int   g_gstart[NG + 1];
__device__ float g_part[NG * 8 * F];
__device__ int   g_bsum[SCAN_NB];
__device__ int   g_boff[SCAN_NB];

// ---------------- CSR build ----------------
__global__ void k_init() {
    int i = blockIdx.x * blockDim.x + threadIdx.x;
    if (i < NN) g_deg[i] = 0;
    if (i <= NG) g_gstart[i] = NN;        // default: empty until boundary found
}

__global__ void k_deg(const int* __restrict__ dst) {
    int t = blockIdx.x * blockDim.x + threadIdx.x;
    if (t < NE / 4) {
        int4 d = reinterpret_cast<const int4*>(dst)[t];
        atomicAdd(&g_deg[d.x], 1);
        atomicAdd(&g_deg[d.y], 1);
        atomicAdd(&g_deg[d.z], 1);
        atomicAdd(&g_deg[d.w], 1);
    }
}

// block-local scan + graph boundary detection (gid is sorted)
__global__ void k_scan_a(const int* __restrict__ gid) {
    __shared__ int sm[SCAN_BLK];
    int tid = threadIdx.x;
    int i = blockIdx.x * SCAN_BLK + tid;
    int v = (i < NN) ? g_deg[i] : 0;
    sm[tid] = v;
    if (i < NN) {
        int g = gid[i];
        if (i == 0 || gid[i - 1] != g) g_gstart[g] = i;
    }
    __syncthreads();
    for (int off = 1; off < SCAN_BLK; off <<= 1) {
        int a = (tid >= off) ? sm[tid - off] : 0;
        __syncthreads();
        sm[tid] += a;
        __syncthreads();
    }
    if (i < NN) g_rowoff[i] = sm[tid] - v;
    if (tid == SCAN_BLK - 1) g_bsum[blockIdx.x] = sm[tid];
}

// scan of block partials + suffix-min fixup for empty graphs
__global__ void k_scan_b() {
    __shared__ int sm[128];
    int tid = threadIdx.x;
    int v = (tid < SCAN_NB) ? g_bsum[tid] : 0;
    sm[tid] = v;
    __syncthreads();
    for (int off = 1; off < 128; off <<= 1) {
        int a = (tid >= off) ? sm[tid - off] : 0;
        __syncthreads();
        sm[tid] += a;
        __syncthreads();
    }
    if (tid < SCAN_NB) g_boff[tid] = sm[tid] - v;
    if (tid == 0) {
        for (int g = NG - 1; g >= 0; g--) {
            int nx = g_gstart[g + 1];
            if (g_gstart[g] > nx) g_gstart[g] = nx;
        }
    }
}

__global__ void k_scan_c() {
    int tid = threadIdx.x;
    int i = blockIdx.x * SCAN_BLK + tid;
    if (i < NN) {
        int r = g_rowoff[i] + g_boff[blockIdx.x];
        g_rowoff[i] = r;
        g_cursor[i] = r;
        g_invdeg[i] = 1.0f / (float)max(g_deg[i], 1);
    }
    if (i == 0) g_rowoff[NN] = NE;
}

__global__ void k_scatter(const int* __restrict__ src, const int* __restrict__ dst) {
    int t = blockIdx.x * blockDim.x + threadIdx.x;
    if (t < NE / 4) {
        int4 d = reinterpret_cast<const int4*>(dst)[t];
        int4 s = reinterpret_cast<const int4*>(src)[t];
        int p0 = atomicAdd(&g_cursor[d.x], 1);
        int p1 = atomicAdd(&g_cursor[d.y], 1);
        int p2 = atomicAdd(&g_cursor[d.z], 1);
        int p3 = atomicAdd(&g_cursor[d.w], 1);
        g_csr[p0] = s.x;
        g_csr[p1] = s.y;
        g_csr[p2] = s.z;
        g_csr[p3] = s.w;
    }
}

// ---------------- tensor-core GEMM: Ybf = bf16( X @ W ) ----------------
// A = bf16(X), B = W split hi+lo. 256-row blocks, 2 m-tiles per warp,
// ldmatrix.x4.trans for B (two n8 fragments per LDSM).
#define PITCHB 272
#define ATILE_BYTES (256 * PITCHB)        // 69632
#define BTILE_BYTES (128 * PITCHB)        // 34816
#define SMEM_GEMM (ATILE_BYTES + 2 * BTILE_BYTES)  // 139264

__device__ __forceinline__ void ldsm_x4(uint32_t addr, uint32_t& r0, uint32_t& r1,
                                        uint32_t& r2, uint32_t& r3) {
    asm volatile("ldmatrix.sync.aligned.m8n8.x4.shared.b16 {%0,%1,%2,%3}, [%4];"
                 : "=r"(r0), "=r"(r1), "=r"(r2), "=r"(r3) : "r"(addr));
}
__device__ __forceinline__ void ldsm_x4t(uint32_t addr, uint32_t& r0, uint32_t& r1,
                                         uint32_t& r2, uint32_t& r3) {
    asm volatile("ldmatrix.sync.aligned.m8n8.x4.trans.shared.b16 {%0,%1,%2,%3}, [%4];"
                 : "=r"(r0), "=r"(r1), "=r"(r2), "=r"(r3) : "r"(addr));
}
__device__ __forceinline__ void mma_bf16(float& c0, float& c1, float& c2, float& c3,
                                         uint32_t a0, uint32_t a1, uint32_t a2, uint32_t a3,
                                         uint32_t b0, uint32_t b1) {
    asm volatile("mma.sync.aligned.m16n8k16.row.col.f32.bf16.bf16.f32 "
                 "{%0,%1,%2,%3},{%4,%5,%6,%7},{%8,%9},{%0,%1,%2,%3};"
                 : "+f"(c0), "+f"(c1), "+f"(c2), "+f"(c3)
                 : "r"(a0), "r"(a1), "r"(a2), "r"(a3), "r"(b0), "r"(b1));
}
__device__ __forceinline__ uint32_t pack2(float x, float y) {
    __nv_bfloat162 h = __floats2bfloat162_rn(x, y);
    return *reinterpret_cast<uint32_t*>(&h);
}
__device__ __forceinline__ uint32_t pack2lo(float x, float y, uint32_t hp) {
    float hx = __uint_as_float((hp & 0xFFFFu) << 16);
    float hy = __uint_as_float(hp & 0xFFFF0000u);
    __nv_bfloat162 h = __floats2bfloat162_rn(x - hx, y - hy);
    return *reinterpret_cast<uint32_t*>(&h);
}

__global__ __launch_bounds__(256, 1) void k_gemm(const float* __restrict__ Xf,
                                                 const __nv_bfloat16* __restrict__ Xb,
                                                 const float* __restrict__ W,
                                                 __nv_bfloat16* __restrict__ Ybf) {
    extern __shared__ char smem[];
    char* sA   = smem;
    char* sBhi = smem + ATILE_BYTES;
    char* sBlo = smem + ATILE_BYTES + BTILE_BYTES;

    int tid = threadIdx.x;
    int base = blockIdx.x * 256;

    // A tile: 256 rows x 128 cols -> bf16
    for (int it = tid; it < 256 * 32; it += 256) {
        int row = it >> 5;
        int c4 = (it & 31) * 4;
        int r = min(base + row, NN - 1);
        uint2 a;
        if (Xb) {
            a = reinterpret_cast<const uint2*>(Xb)[(size_t)r * 32 + (c4 >> 2)];
        } else {
            float4 v = *reinterpret_cast<const float4*>(Xf + (size_t)r * F + c4);
            a = make_uint2(pack2(v.x, v.y), pack2(v.z, v.w));
        }
        *reinterpret_cast<uint2*>(sA + row * PITCHB + c4 * 2) = a;
    }
    // W tile: hi + lo
    for (int it = tid; it < 128 * 32; it += 256) {
        int row = it >> 5;
        int c4 = (it & 31) * 4;
        float4 v = *reinterpret_cast<const float4*>(W + row * F + c4);
        uint32_t h0 = pack2(v.x, v.y), h1 = pack2(v.z, v.w);
        uint32_t l0 = pack2lo(v.x, v.y, h0), l1 = pack2lo(v.z, v.w, h1);
        *reinterpret_cast<uint2*>(sBhi + row * PITCHB + c4 * 2) = make_uint2(h0, h1);
        *reinterpret_cast<uint2*>(sBlo + row * PITCHB + c4 * 2) = make_uint2(l0, l1);
    }
    __syncthreads();

    int lane = tid & 31;
    int w = tid >> 5;
    int m0 = w * 32;          // tile 0 rows m0..m0+15, tile 1 rows m0+16..m0+31

    uint32_t sA_u   = (uint32_t)__cvta_generic_to_shared(sA);
    uint32_t sBhi_u = (uint32_t)__cvta_generic_to_shared(sBhi);
    uint32_t sBlo_u = (uint32_t)__cvta_generic_to_shared(sBlo);

    uint32_t arow = (uint32_t)((lane & 7) + ((lane >> 3) & 1) * 8);
    uint32_t aoff0 = (uint32_t)((m0 + arow) * PITCHB + (lane >> 4) * 16);
    uint32_t aoff1 = aoff0 + 16 * PITCHB;
    // B x4.trans: lanes 0-15 -> first n8 block, lanes 16-31 -> second n8 block
    uint32_t boff = (uint32_t)((lane & 15) * PITCHB + (lane >> 4) * 16);

    float acc[2][16][4];
#pragma unroll
    for (int t = 0; t < 2; t++)
#pragma unroll
        for (int j = 0; j < 16; j++)
#pragma unroll
            for (int q = 0; q < 4; q++) acc[t][j][q] = 0.0f;

#pragma unroll
    for (int s = 0; s < 8; s++) {
        uint32_t a00, a01, a02, a03, a10, a11, a12, a13;
        ldsm_x4(sA_u + aoff0 + s * 32, a00, a01, a02, a03);
        ldsm_x4(sA_u + aoff1 + s * 32, a10, a11, a12, a13);
        uint32_t bbase = boff + s * 16 * PITCHB;
#pragma unroll
        for (int j2 = 0; j2 < 8; j2++) {
            int j = j2 * 2;
            uint32_t bh0, bh1, bh2, bh3, bl0, bl1, bl2, bl3;
            ldsm_x4t(sBhi_u + bbase + j2 * 32, bh0, bh1, bh2, bh3);
            mma_bf16(acc[0][j][0], acc[0][j][1], acc[0][j][2], acc[0][j][3],
                     a00, a01, a02, a03, bh0, bh1);
            mma_bf16(acc[1][j][0], acc[1][j][1], acc[1][j][2], acc[1][j][3],
                     a10, a11, a12, a13, bh0, bh1);
            mma_bf16(acc[0][j+1][0], acc[0][j+1][1], acc[0][j+1][2], acc[0][j+1][3],
                     a00, a01, a02, a03, bh2, bh3);
            mma_bf16(acc[1][j+1][0], acc[1][j+1][1], acc[1][j+1][2], acc[1][j+1][3],
                     a10, a11, a12, a13, bh2, bh3);
            ldsm_x4t(sBlo_u + bbase + j2 * 32, bl0, bl1, bl2, bl3);
            mma_bf16(acc[0][j][0], acc[0][j][1], acc[0][j][2], acc[0][j][3],
                     a00, a01, a02, a03, bl0, bl1);
            mma_bf16(acc[1][j][0], acc[1][j][1], acc[1][j][2], acc[1][j][3],
                     a10, a11, a12, a13, bl0, bl1);
            mma_bf16(acc[0][j+1][0], acc[0][j+1][1], acc[0][j+1][2], acc[0][j+1][3],
                     a00, a01, a02, a03, bl2, bl3);
            mma_bf16(acc[1][j+1][0], acc[1][j+1][1], acc[1][j+1][2], acc[1][j+1][3],
                     a10, a11, a12, a13, bl2, bl3);
        }
    }

    int gq = lane >> 2;
    int tq = lane & 3;
#pragma unroll
    for (int t = 0; t < 2; t++) {
        int r0 = base + m0 + t * 16 + gq;
        int r1 = r0 + 8;
#pragma unroll
        for (int j = 0; j < 16; j++) {
            int col = j * 8 + tq * 2;
            if (r0 < NN)
                *reinterpret_cast<uint32_t*>(Ybf + (size_t)r0 * F + col) =
                    pack2(acc[t][j][0], acc[t][j][1]);
            if (r1 < NN)
                *reinterpret_cast<uint32_t*>(Ybf + (size_t)r1 * F + col) =
                    pack2(acc[t][j][2], acc[t][j][3]);
        }
    }
}

// ---------------- aggregation ----------------
__device__ __forceinline__ void acc_bf2(float& ax, float& ay, float& az, float& aw,
                                        uint2 u) {
    ax += __uint_as_float(u.x << 16);
    ay += __uint_as_float(u.x & 0xFFFF0000u);
    az += __uint_as_float(u.y << 16);
    aw += __uint_as_float(u.y & 0xFFFF0000u);
}

__global__ __launch_bounds__(256) void k_agg(const __nv_bfloat16* __restrict__ Ybf,
                                             const float* __restrict__ bias,
                                             __nv_bfloat16* __restrict__ Hbf) {
    int gw   = (blockIdx.x * blockDim.x + threadIdx.x) >> 5;
    int lane = threadIdx.x & 31;
    if (gw >= NN) return;

    int beg = g_rowoff[gw];
    int end = g_rowoff[gw + 1];
    const uint2* __restrict__ Yb2 = reinterpret_cast<const uint2*>(Ybf);

    float ax = 0.f, ay = 0.f, az = 0.f, aw = 0.f;
    int e = beg;
    for (; e + 7 < end; e += 8) {
        int s0 = g_csr[e],     s1 = g_csr[e + 1], s2 = g_csr[e + 2], s3 = g_csr[e + 3];
        int s4 = g_csr[e + 4], s5 = g_csr[e + 5], s6 = g_csr[e + 6], s7 = g_csr[e + 7];
        uint2 u0 = Yb2[(size_t)s0 * 32 + lane];
        uint2 u1 = Yb2[(size_t)s1 * 32 + lane];
        uint2 u2 = Yb2[(size_t)s2 * 32 + lane];
        uint2 u3 = Yb2[(size_t)s3 * 32 + lane];
        uint2 u4 = Yb2[(size_t)s4 * 32 + lane];
        uint2 u5 = Yb2[(size_t)s5 * 32 + lane];
        uint2 u6 = Yb2[(size_t)s6 * 32 + lane];
        uint2 u7 = Yb2[(size_t)s7 * 32 + lane];
        acc_bf2(ax, ay, az, aw, u0);
        acc_bf2(ax, ay, az, aw, u1);
        acc_bf2(ax, ay, az, aw, u2);
        acc_bf2(ax, ay, az, aw, u3);
        acc_bf2(ax, ay, az, aw, u4);
        acc_bf2(ax, ay, az, aw, u5);
        acc_bf2(ax, ay, az, aw, u6);
        acc_bf2(ax, ay, az, aw, u7);
    }
    for (; e + 3 < end; e += 4) {
        int s0 = g_csr[e], s1 = g_csr[e + 1], s2 = g_csr[e + 2], s3 = g_csr[e + 3];
        uint2 u0 = Yb2[(size_t)s0 * 32 + lane];
        uint2 u1 = Yb2[(size_t)s1 * 32 + lane];
        uint2 u2 = Yb2[(size_t)s2 * 32 + lane];
        uint2 u3 = Yb2[(size_t)s3 * 32 + lane];
        acc_bf2(ax, ay, az, aw, u0);
        acc_bf2(ax, ay, az, aw, u1);
        acc_bf2(ax, ay, az, aw, u2);
        acc_bf2(ax, ay, az, aw, u3);
    }
    for (; e < end; e++) {
        uint2 u = Yb2[(size_t)g_csr[e] * 32 + lane];
        acc_bf2(ax, ay, az, aw, u);
    }

    float inv = g_invdeg[gw];
    uint2 us = Yb2[(size_t)gw * 32 + lane];
    float sx = __uint_as_float(us.x << 16);
    float sy = __uint_as_float(us.x & 0xFFFF0000u);
    float sz = __uint_as_float(us.y << 16);
    float sw = __uint_as_float(us.y & 0xFFFF0000u);
    float4 bb = reinterpret_cast<const float4*>(bias)[lane];
    float hx = fmaxf(fmaf(ax, inv, sx) + bb.x, 0.f);
    float hy = fmaxf(fmaf(ay, inv, sy) + bb.y, 0.f);
    float hz = fmaxf(fmaf(az, inv, sz) + bb.z, 0.f);
    float hw = fmaxf(fmaf(aw, inv, sw) + bb.w, 0.f);
    reinterpret_cast<uint2*>(Hbf)[(size_t)gw * 32 + lane] =
        make_uint2(pack2(hx, hy), pack2(hz, hw));
}

// ---------------- pooling stage 1 ----------------
__global__ void k_pool1(const __nv_bfloat16* __restrict__ H) {
    int bx = blockIdx.x;            // NG*8 blocks
    int g = bx >> 3, c = bx & 7;
    int tid = threadIdx.x;          // 512
    int col2 = tid & 63;
    int sub = tid >> 6;             // 0..7
    int s = g_gstart[g];
    int e = g_gstart[g + 1];
    const uint32_t* __restrict__ H2 = reinterpret_cast<const uint32_t*>(H);
    float px = 0.f, py = 0.f;
    for (int r = s + c * 8 + sub; r < e; r += 64) {
        uint32_t u = H2[(size_t)r * 64 + col2];
        px += __uint_as_float(u << 16);
        py += __uint_as_float(u & 0xFFFF0000u);
    }
    __shared__ float smx[512], smy[512];
    smx[tid] = px;
    smy[tid] = py;
    __syncthreads();
    if (tid < 64) {
        float sx = 0.f, sy = 0.f;
#pragma unroll
        for (int k = 0; k < 8; k++) {
            sx += smx[k * 64 + tid];
            sy += smy[k * 64 + tid];
        }
        *reinterpret_cast<float2*>(&g_part[bx * F + tid * 2]) = make_float2(sx, sy);
    }
}

// ---------------- pooling finalize + decoder (fused) ----------------
__global__ void k_dec(const float* __restrict__ Wd1, const float* __restrict__ bd1,
                      const float* __restrict__ Wd2, const float* __restrict__ bd2,
                      float* __restrict__ out) {
    int g = blockIdx.x;
    int tid = threadIdx.x;          // 128
    __shared__ float hgs[F], ts[F];

    float s = 0.f;
#pragma unroll
    for (int c = 0; c < 8; c++) s += g_part[(g * 8 + c) * F + tid];
    int cnt = g_gstart[g + 1] - g_gstart[g];
    float mean = s / (float)max(cnt, 1);
    out[g * F + tid] = mean;
    hgs[tid] = mean;
    __syncthreads();

    float s0 = 0.f, s1 = 0.f, s2 = 0.f, s3 = 0.f;
#pragma unroll 8
    for (int k = 0; k < F; k += 4) {
        s0 = fmaf(hgs[k],     Wd1[(k)     * F + tid], s0);
        s1 = fmaf(hgs[k + 1], Wd1[(k + 1) * F + tid], s1);
        s2 = fmaf(hgs[k + 2], Wd1[(k + 2) * F + tid], s2);
        s3 = fmaf(hgs[k + 3], Wd1[(k + 3) * F + tid], s3);
    }
    ts[tid] = fmaxf((s0 + s1) + (s2 + s3) + bd1[tid], 0.f);
    __syncthreads();
    if (tid < OUTF) {
        float o0 = 0.f, o1 = 0.f, o2 = 0.f, o3 = 0.f;
#pragma unroll 8
        for (int k = 0; k < F; k += 4) {
            o0 = fmaf(ts[k],     Wd2[(k)     * OUTF + tid], o0);
            o1 = fmaf(ts[k + 1], Wd2[(k + 1) * OUTF + tid], o1);
            o2 = fmaf(ts[k + 2], Wd2[(k + 2) * OUTF + tid], o2);
            o3 = fmaf(ts[k + 3], Wd2[(k + 3) * OUTF + tid], o3);
        }
        out[NG * F + g * OUTF + tid] = (o0 + o1) + (o2 + o3) + bd2[tid];
    }
}

// ---------------- launch ----------------
extern "C" void kernel_launch(void* const* d_in, const int* in_sizes, int n_in,
                              void* d_out, int out_size) {
    const float* feat = (const float*)d_in[0];
    const int*   src  = (const int*)d_in[1];
    const int*   dst  = (const int*)d_in[2];
    const int*   gid  = (const int*)d_in[3];
    const float* W1   = (const float*)d_in[4];
    const float* b1   = (const float*)d_in[5];
    const float* W2   = (const float*)d_in[6];
    const float* b2   = (const float*)d_in[7];
    const float* Wd1  = (const float*)d_in[8];
    const float* bd1  = (const float*)d_in[9];
    const float* Wd2  = (const float*)d_in[10];
    const float* bd2  = (const float*)d_in[11];
    float* out = (float*)d_out;

    __nv_bfloat16 *ybf, *hbf;
    cudaGetSymbolAddress((void**)&ybf, g_ybf);
    cudaGetSymbolAddress((void**)&hbf, g_hbf);

    cudaFuncSetAttribute(k_gemm, cudaFuncAttributeMaxDynamicSharedMemorySize, SMEM_GEMM);

    // lazily-created side stream + events (created on first, non-capture call;
    // identical captured work every call)
    static cudaStream_t s_side = nullptr;
    static cudaEvent_t e_fork = nullptr, e_join = nullptr;
    if (s_side == nullptr) {
        cudaStreamCreateWithFlags(&s_side, cudaStreamNonBlocking);
        cudaEventCreateWithFlags(&e_fork, cudaEventDisableTiming);
        cudaEventCreateWithFlags(&e_join, cudaEventDisableTiming);
    }

    int gblocks = (NN + 255) / 256;

    // fork: GEMM1 (depends only on feat/W1) overlaps the CSR build
    cudaEventRecord(e_fork, 0);
    cudaStreamWaitEvent(s_side, e_fork, 0);
    k_gemm<<<gblocks, 256, SMEM_GEMM, s_side>>>(feat, nullptr, W1, ybf);
    cudaEventRecord(e_join, s_side);

    // CSR build on main stream (concurrent with GEMM1)
    k_init<<<(NN + 255) / 256, 256>>>();
    k_deg<<<(NE / 4 + 255) / 256, 256>>>(dst);
    k_scan_a<<<SCAN_NB, SCAN_BLK>>>(gid);
    k_scan_b<<<1, 128>>>();
    k_scan_c<<<SCAN_NB, SCAN_BLK>>>();
    k_scatter<<<(NE / 4 + 255) / 256, 256>>>(src, dst);

    // join: agg1 needs both CSR and ybf
    cudaStreamWaitEvent(0, e_join, 0);
    k_agg<<<(NN * 32 + 255) / 256, 256>>>(ybf, b1, hbf);

    // layer 2
    k_gemm<<<gblocks, 256, SMEM_GEMM>>>(nullptr, hbf, W2, ybf);
    k_agg<<<(NN * 32 + 255) / 256, 256>>>(ybf, b2, hbf);

    // pooling + decoder
    k_pool1<<<NG * 8, 512>>>(hbf);
    k_dec<<<NG, 128>>>(Wd1, bd1, Wd2, bd2, out);
}

// round 6
// speedup vs baseline: 4.0968x; 1.0272x over previous
#include <cuda_runtime.h>
#include <cuda_bf16.h>
#include <cstdint>

#define NN 100000
#define NE 1600000
#define F  128
#define NG 64
#define OUTF 64

#define SCAN_BLK 1024
#define SCAN_NB  ((NN + SCAN_BLK - 1) / SCAN_BLK)   // 98

// ---------------- scratch ----------------
__device__ __nv_bfloat16 g_ybf[NN * F];       // Y = X@W (bf16)
__device__ __nv_bfloat16 g_hbf[NN * F];       // layer output H (bf16)
__device__ int   g_deg[NN];
__device__ int   g_rowoff[NN + 1];
__device__ int   g_cursor[NN];
__device__ int   g_csr[NE];
__device__ float g_invdeg[NN];
__device__ int   g_gstart[NG + 1];
__device__ float g_part[NG * 8 * F];
__device__ int   g_bsum[SCAN_NB];

// ---------------- CSR build ----------------
// (g_deg zeroed and g_gstart filled with 0x7f7f7f7f via cudaMemsetAsync)

__global__ void k_deg(const int* __restrict__ dst) {
    int t = blockIdx.x * blockDim.x + threadIdx.x;
    if (t < NE / 4) {
        int4 d = reinterpret_cast<const int4*>(dst)[t];
        atomicAdd(&g_deg[d.x], 1);
        atomicAdd(&g_deg[d.y], 1);
        atomicAdd(&g_deg[d.z], 1);
        atomicAdd(&g_deg[d.w], 1);
    }
}

// block-local scan + graph boundary detection (gid is sorted)
__global__ void k_scan_a(const int* __restrict__ gid) {
    __shared__ int sm[SCAN_BLK];
    int tid = threadIdx.x;
    int i = blockIdx.x * SCAN_BLK + tid;
    int v = (i < NN) ? g_deg[i] : 0;
    sm[tid] = v;
    if (i < NN) {
        int g = gid[i];
        if (i == 0 || gid[i - 1] != g) g_gstart[g] = i;
    }
    __syncthreads();
    for (int off = 1; off < SCAN_BLK; off <<= 1) {
        int a = (tid >= off) ? sm[tid - off] : 0;
        __syncthreads();
        sm[tid] += a;
        __syncthreads();
    }
    if (i < NN) g_rowoff[i] = sm[tid] - v;     // block-local exclusive
    if (tid == SCAN_BLK - 1) g_bsum[blockIdx.x] = sm[tid];
}

// each block reduces its own prefix of block partials, then finalizes
__global__ void k_scan_c() {
    __shared__ int red[128];
    __shared__ int s_boff;
    int tid = threadIdx.x;
    int bid = blockIdx.x;
    if (tid < 128) red[tid] = (tid < bid) ? g_bsum[tid] : 0;   // bid <= 97
    __syncthreads();
    for (int off = 64; off >= 1; off >>= 1) {
        if (tid < off) red[tid] += red[tid + off];
        __syncthreads();
    }
    if (tid == 0) s_boff = red[0];
    __syncthreads();

    int i = bid * SCAN_BLK + tid;
    if (i < NN) {
        int r = g_rowoff[i] + s_boff;
        g_rowoff[i] = r;
        g_cursor[i] = r;
        g_invdeg[i] = 1.0f / (float)max(g_deg[i], 1);
    }
    if (i == 0) g_rowoff[NN] = NE;
}

__global__ void k_scatter(const int* __restrict__ src, const int* __restrict__ dst) {
    int t = blockIdx.x * blockDim.x + threadIdx.x;
    // fold gstart suffix-min fixup into this kernel (runs after scan_a globally)
    if (blockIdx.x == 0 && threadIdx.x == 0) {
        g_gstart[NG] = NN;
        for (int g = NG - 1; g >= 0; g--) {
            int nx = g_gstart[g + 1];
            if (g_gstart[g] > nx) g_gstart[g] = nx;
        }
    }
    if (t < NE / 4) {
        int4 d = reinterpret_cast<const int4*>(dst)[t];
        int4 s = reinterpret_cast<const int4*>(src)[t];
        int p0 = atomicAdd(&g_cursor[d.x], 1);
        int p1 = atomicAdd(&g_cursor[d.y], 1);
        int p2 = atomicAdd(&g_cursor[d.z], 1);
        int p3 = atomicAdd(&g_cursor[d.w], 1);
        g_csr[p0] = s.x;
        g_csr[p1] = s.y;
        g_csr[p2] = s.z;
        g_csr[p3] = s.w;
    }
}

// ---------------- tensor-core GEMM: Ybf = bf16( X @ W ) ----------------
#define PITCHB 272
#define ATILE_BYTES (256 * PITCHB)
#define BTILE_BYTES (128 * PITCHB)
#define SMEM_GEMM (ATILE_BYTES + 2 * BTILE_BYTES)  // 139264

__device__ __forceinline__ void ldsm_x4(uint32_t addr, uint32_t& r0, uint32_t& r1,
                                        uint32_t& r2, uint32_t& r3) {
    asm volatile("ldmatrix.sync.aligned.m8n8.x4.shared.b16 {%0,%1,%2,%3}, [%4];"
                 : "=r"(r0), "=r"(r1), "=r"(r2), "=r"(r3) : "r"(addr));
}
__device__ __forceinline__ void ldsm_x4t(uint32_t addr, uint32_t& r0, uint32_t& r1,
                                         uint32_t& r2, uint32_t& r3) {
    asm volatile("ldmatrix.sync.aligned.m8n8.x4.trans.shared.b16 {%0,%1,%2,%3}, [%4];"
                 : "=r"(r0), "=r"(r1), "=r"(r2), "=r"(r3) : "r"(addr));
}
__device__ __forceinline__ void mma_bf16(float& c0, float& c1, float& c2, float& c3,
                                         uint32_t a0, uint32_t a1, uint32_t a2, uint32_t a3,
                                         uint32_t b0, uint32_t b1) {
    asm volatile("mma.sync.aligned.m16n8k16.row.col.f32.bf16.bf16.f32 "
                 "{%0,%1,%2,%3},{%4,%5,%6,%7},{%8,%9},{%0,%1,%2,%3};"
                 : "+f"(c0), "+f"(c1), "+f"(c2), "+f"(c3)
                 : "r"(a0), "r"(a1), "r"(a2), "r"(a3), "r"(b0), "r"(b1));
}
__device__ __forceinline__ uint32_t pack2(float x, float y) {
    __nv_bfloat162 h = __floats2bfloat162_rn(x, y);
    return *reinterpret_cast<uint32_t*>(&h);
}
__device__ __forceinline__ uint32_t pack2lo(float x, float y, uint32_t hp) {
    float hx = __uint_as_float((hp & 0xFFFFu) << 16);
    float hy = __uint_as_float(hp & 0xFFFF0000u);
    __nv_bfloat162 h = __floats2bfloat162_rn(x - hx, y - hy);
    return *reinterpret_cast<uint32_t*>(&h);
}

__global__ __launch_bounds__(256, 1) void k_gemm(const float* __restrict__ Xf,
                                                 const __nv_bfloat16* __restrict__ Xb,
                                                 const float* __restrict__ W,
                                                 __nv_bfloat16* __restrict__ Ybf) {
    extern __shared__ char smem[];
    char* sA   = smem;
    char* sBhi = smem + ATILE_BYTES;
    char* sBlo = smem + ATILE_BYTES + BTILE_BYTES;

    int tid = threadIdx.x;
    int base = blockIdx.x * 256;

    for (int it = tid; it < 256 * 32; it += 256) {
        int row = it >> 5;
        int c4 = (it & 31) * 4;
        int r = min(base + row, NN - 1);
        uint2 a;
        if (Xb) {
            a = reinterpret_cast<const uint2*>(Xb)[(size_t)r * 32 + (c4 >> 2)];
        } else {
            float4 v = *reinterpret_cast<const float4*>(Xf + (size_t)r * F + c4);
            a = make_uint2(pack2(v.x, v.y), pack2(v.z, v.w));
        }
        *reinterpret_cast<uint2*>(sA + row * PITCHB + c4 * 2) = a;
    }
    for (int it = tid; it < 128 * 32; it += 256) {
        int row = it >> 5;
        int c4 = (it & 31) * 4;
        float4 v = *reinterpret_cast<const float4*>(W + row * F + c4);
        uint32_t h0 = pack2(v.x, v.y), h1 = pack2(v.z, v.w);
        uint32_t l0 = pack2lo(v.x, v.y, h0), l1 = pack2lo(v.z, v.w, h1);
        *reinterpret_cast<uint2*>(sBhi + row * PITCHB + c4 * 2) = make_uint2(h0, h1);
        *reinterpret_cast<uint2*>(sBlo + row * PITCHB + c4 * 2) = make_uint2(l0, l1);
    }
    __syncthreads();

    int lane = tid & 31;
    int w = tid >> 5;
    int m0 = w * 32;

    uint32_t sA_u   = (uint32_t)__cvta_generic_to_shared(sA);
    uint32_t sBhi_u = (uint32_t)__cvta_generic_to_shared(sBhi);
    uint32_t sBlo_u = (uint32_t)__cvta_generic_to_shared(sBlo);

    uint32_t arow = (uint32_t)((lane & 7) + ((lane >> 3) & 1) * 8);
    uint32_t aoff0 = (uint32_t)((m0 + arow) * PITCHB + (lane >> 4) * 16);
    uint32_t aoff1 = aoff0 + 16 * PITCHB;
    uint32_t boff = (uint32_t)((lane & 15) * PITCHB + (lane >> 4) * 16);

    float acc[2][16][4];
#pragma unroll
    for (int t = 0; t < 2; t++)
#pragma unroll
        for (int j = 0; j < 16; j++)
#pragma unroll
            for (int q = 0; q < 4; q++) acc[t][j][q] = 0.0f;

#pragma unroll
    for (int s = 0; s < 8; s++) {
        uint32_t a00, a01, a02, a03, a10, a11, a12, a13;
        ldsm_x4(sA_u + aoff0 + s * 32, a00, a01, a02, a03);
        ldsm_x4(sA_u + aoff1 + s * 32, a10, a11, a12, a13);
        uint32_t bbase = boff + s * 16 * PITCHB;
#pragma unroll
        for (int j2 = 0; j2 < 8; j2++) {
            int j = j2 * 2;
            uint32_t bh0, bh1, bh2, bh3, bl0, bl1, bl2, bl3;
            ldsm_x4t(sBhi_u + bbase + j2 * 32, bh0, bh1, bh2, bh3);
            mma_bf16(acc[0][j][0], acc[0][j][1], acc[0][j][2], acc[0][j][3],
                     a00, a01, a02, a03, bh0, bh1);
            mma_bf16(acc[1][j][0], acc[1][j][1], acc[1][j][2], acc[1][j][3],
                     a10, a11, a12, a13, bh0, bh1);
            mma_bf16(acc[0][j+1][0], acc[0][j+1][1], acc[0][j+1][2], acc[0][j+1][3],
                     a00, a01, a02, a03, bh2, bh3);
            mma_bf16(acc[1][j+1][0], acc[1][j+1][1], acc[1][j+1][2], acc[1][j+1][3],
                     a10, a11, a12, a13, bh2, bh3);
            ldsm_x4t(sBlo_u + bbase + j2 * 32, bl0, bl1, bl2, bl3);
            mma_bf16(acc[0][j][0], acc[0][j][1], acc[0][j][2], acc[0][j][3],
                     a00, a01, a02, a03, bl0, bl1);
            mma_bf16(acc[1][j][0], acc[1][j][1], acc[1][j][2], acc[1][j][3],
                     a10, a11, a12, a13, bl0, bl1);
            mma_bf16(acc[0][j+1][0], acc[0][j+1][1], acc[0][j+1][2], acc[0][j+1][3],
                     a00, a01, a02, a03, bl2, bl3);
            mma_bf16(acc[1][j+1][0], acc[1][j+1][1], acc[1][j+1][2], acc[1][j+1][3],
                     a10, a11, a12, a13, bl2, bl3);
        }
    }

    int gq = lane >> 2;
    int tq = lane & 3;
#pragma unroll
    for (int t = 0; t < 2; t++) {
        int r0 = base + m0 + t * 16 + gq;
        int r1 = r0 + 8;
#pragma unroll
        for (int j = 0; j < 16; j++) {
            int col = j * 8 + tq * 2;
            if (r0 < NN)
                *reinterpret_cast<uint32_t*>(Ybf + (size_t)r0 * F + col) =
                    pack2(acc[t][j][0], acc[t][j][1]);
            if (r1 < NN)
                *reinterpret_cast<uint32_t*>(Ybf + (size_t)r1 * F + col) =
                    pack2(acc[t][j][2], acc[t][j][3]);
        }
    }
}

// ---------------- aggregation: half-warp (16 lanes) per node, LDG.128 ------
__device__ __forceinline__ float bfl(uint32_t x) { return __uint_as_float(x << 16); }
__device__ __forceinline__ float bfh(uint32_t x) { return __uint_as_float(x & 0xFFFF0000u); }

__device__ __forceinline__ void acc8(float a[8], uint4 u) {
    a[0] += bfl(u.x); a[1] += bfh(u.x);
    a[2] += bfl(u.y); a[3] += bfh(u.y);
    a[4] += bfl(u.z); a[5] += bfh(u.z);
    a[6] += bfl(u.w); a[7] += bfh(u.w);
}

__global__ __launch_bounds__(256) void k_agg(const __nv_bfloat16* __restrict__ Ybf,
                                             const float* __restrict__ bias,
                                             __nv_bfloat16* __restrict__ Hbf) {
    int node   = (blockIdx.x * blockDim.x + threadIdx.x) >> 4;
    int lane16 = threadIdx.x & 15;
    if (node >= NN) return;

    int beg = g_rowoff[node];
    int end = g_rowoff[node + 1];
    const uint4* __restrict__ Yb4 = reinterpret_cast<const uint4*>(Ybf);

    float a[8];
#pragma unroll
    for (int q = 0; q < 8; q++) a[q] = 0.0f;

    int e = beg;
    for (; e + 7 < end; e += 8) {
        int s0 = g_csr[e],     s1 = g_csr[e + 1], s2 = g_csr[e + 2], s3 = g_csr[e + 3];
        int s4 = g_csr[e + 4], s5 = g_csr[e + 5], s6 = g_csr[e + 6], s7 = g_csr[e + 7];
        uint4 u0 = Yb4[(size_t)s0 * 16 + lane16];
        uint4 u1 = Yb4[(size_t)s1 * 16 + lane16];
        uint4 u2 = Yb4[(size_t)s2 * 16 + lane16];
        uint4 u3 = Yb4[(size_t)s3 * 16 + lane16];
        uint4 u4 = Yb4[(size_t)s4 * 16 + lane16];
        uint4 u5 = Yb4[(size_t)s5 * 16 + lane16];
        uint4 u6 = Yb4[(size_t)s6 * 16 + lane16];
        uint4 u7 = Yb4[(size_t)s7 * 16 + lane16];
        acc8(a, u0); acc8(a, u1); acc8(a, u2); acc8(a, u3);
        acc8(a, u4); acc8(a, u5); acc8(a, u6); acc8(a, u7);
    }
    for (; e + 3 < end; e += 4) {
        int s0 = g_csr[e], s1 = g_csr[e + 1], s2 = g_csr[e + 2], s3 = g_csr[e + 3];
        uint4 u0 = Yb4[(size_t)s0 * 16 + lane16];
        uint4 u1 = Yb4[(size_t)s1 * 16 + lane16];
        uint4 u2 = Yb4[(size_t)s2 * 16 + lane16];
        uint4 u3 = Yb4[(size_t)s3 * 16 + lane16];
        acc8(a, u0); acc8(a, u1); acc8(a, u2); acc8(a, u3);
    }
    for (; e < end; e++) {
        uint4 u = Yb4[(size_t)g_csr[e] * 16 + lane16];
        acc8(a, u);
    }

    float inv = g_invdeg[node];
    uint4 us = Yb4[(size_t)node * 16 + lane16];
    float s0 = bfl(us.x), s1 = bfh(us.x), s2 = bfl(us.y), s3 = bfh(us.y);
    float s4 = bfl(us.z), s5 = bfh(us.z), s6 = bfl(us.w), s7 = bfh(us.w);
    const float4* __restrict__ b4 = reinterpret_cast<const float4*>(bias);
    float4 bb0 = b4[lane16 * 2];
    float4 bb1 = b4[lane16 * 2 + 1];
    float h0 = fmaxf(fmaf(a[0], inv, s0) + bb0.x, 0.f);
    float h1 = fmaxf(fmaf(a[1], inv, s1) + bb0.y, 0.f);
    float h2 = fmaxf(fmaf(a[2], inv, s2) + bb0.z, 0.f);
    float h3 = fmaxf(fmaf(a[3], inv, s3) + bb0.w, 0.f);
    float h4 = fmaxf(fmaf(a[4], inv, s4) + bb1.x, 0.f);
    float h5 = fmaxf(fmaf(a[5], inv, s5) + bb1.y, 0.f);
    float h6 = fmaxf(fmaf(a[6], inv, s6) + bb1.z, 0.f);
    float h7 = fmaxf(fmaf(a[7], inv, s7) + bb1.w, 0.f);
    reinterpret_cast<uint4*>(Hbf)[(size_t)node * 16 + lane16] =
        make_uint4(pack2(h0, h1), pack2(h2, h3), pack2(h4, h5), pack2(h6, h7));
}

// ---------------- pooling stage 1 ----------------
__global__ void k_pool1(const __nv_bfloat16* __restrict__ H) {
    int bx = blockIdx.x;            // NG*8 blocks
    int g = bx >> 3, c = bx & 7;
    int tid = threadIdx.x;          // 512
    int col2 = tid & 63;
    int sub = tid >> 6;             // 0..7
    int s = g_gstart[g];
    int e = g_gstart[g + 1];
    const uint32_t* __restrict__ H2 = reinterpret_cast<const uint32_t*>(H);
    float px = 0.f, py = 0.f;
    for (int r = s + c * 8 + sub; r < e; r += 64) {
        uint32_t u = H2[(size_t)r * 64 + col2];
        px += bfl(u);
        py += bfh(u);
    }
    __shared__ float smx[512], smy[512];
    smx[tid] = px;
    smy[tid] = py;
    __syncthreads();
    if (tid < 64) {
        float sx = 0.f, sy = 0.f;
#pragma unroll
        for (int k = 0; k < 8; k++) {
            sx += smx[k * 64 + tid];
            sy += smy[k * 64 + tid];
        }
        *reinterpret_cast<float2*>(&g_part[bx * F + tid * 2]) = make_float2(sx, sy);
    }
}

// ---------------- pooling finalize + decoder (fused) ----------------
__global__ void k_dec(const float* __restrict__ Wd1, const float* __restrict__ bd1,
                      const float* __restrict__ Wd2, const float* __restrict__ bd2,
                      float* __restrict__ out) {
    int g = blockIdx.x;
    int tid = threadIdx.x;          // 128
    __shared__ float hgs[F], ts[F];

    float s = 0.f;
#pragma unroll
    for (int c = 0; c < 8; c++) s += g_part[(g * 8 + c) * F + tid];
    int cnt = g_gstart[g + 1] - g_gstart[g];
    float mean = s / (float)max(cnt, 1);
    out[g * F + tid] = mean;
    hgs[tid] = mean;
    __syncthreads();

    float s0 = 0.f, s1 = 0.f, s2 = 0.f, s3 = 0.f;
#pragma unroll 8
    for (int k = 0; k < F; k += 4) {
        s0 = fmaf(hgs[k],     Wd1[(k)     * F + tid], s0);
        s1 = fmaf(hgs[k + 1], Wd1[(k + 1) * F + tid], s1);
        s2 = fmaf(hgs[k + 2], Wd1[(k + 2) * F + tid], s2);
        s3 = fmaf(hgs[k + 3], Wd1[(k + 3) * F + tid], s3);
    }
    ts[tid] = fmaxf((s0 + s1) + (s2 + s3) + bd1[tid], 0.f);
    __syncthreads();
    if (tid < OUTF) {
        float o0 = 0.f, o1 = 0.f, o2 = 0.f, o3 = 0.f;
#pragma unroll 8
        for (int k = 0; k < F; k += 4) {
            o0 = fmaf(ts[k],     Wd2[(k)     * OUTF + tid], o0);
            o1 = fmaf(ts[k + 1], Wd2[(k + 1) * OUTF + tid], o1);
            o2 = fmaf(ts[k + 2], Wd2[(k + 2) * OUTF + tid], o2);
            o3 = fmaf(ts[k + 3], Wd2[(k + 3) * OUTF + tid], o3);
        }
        out[NG * F + g * OUTF + tid] = (o0 + o1) + (o2 + o3) + bd2[tid];
    }
}

// ---------------- launch ----------------
extern "C" void kernel_launch(void* const* d_in, const int* in_sizes, int n_in,
                              void* d_out, int out_size) {
    const float* feat = (const float*)d_in[0];
    const int*   src  = (const int*)d_in[1];
    const int*   dst  = (const int*)d_in[2];
    const int*   gid  = (const int*)d_in[3];
    const float* W1   = (const float*)d_in[4];
    const float* b1   = (const float*)d_in[5];
    const float* W2   = (const float*)d_in[6];
    const float* b2   = (const float*)d_in[7];
    const float* Wd1  = (const float*)d_in[8];
    const float* bd1  = (const float*)d_in[9];
    const float* Wd2  = (const float*)d_in[10];
    const float* bd2  = (const float*)d_in[11];
    float* out = (float*)d_out;

    __nv_bfloat16 *ybf, *hbf;
    void *degp, *gstartp;
    cudaGetSymbolAddress((void**)&ybf, g_ybf);
    cudaGetSymbolAddress((void**)&hbf, g_hbf);
    cudaGetSymbolAddress(&degp, g_deg);
    cudaGetSymbolAddress(&gstartp, g_gstart);

    cudaFuncSetAttribute(k_gemm, cudaFuncAttributeMaxDynamicSharedMemorySize, SMEM_GEMM);

    static cudaStream_t s_side = nullptr;
    static cudaEvent_t e_fork = nullptr, e_join = nullptr;
    if (s_side == nullptr) {
        cudaStreamCreateWithFlags(&s_side, cudaStreamNonBlocking);
        cudaEventCreateWithFlags(&e_fork, cudaEventDisableTiming);
        cudaEventCreateWithFlags(&e_join, cudaEventDisableTiming);
    }

    int gblocks = (NN + 255) / 256;

    // fork: GEMM1 overlaps the CSR build
    cudaEventRecord(e_fork, 0);
    cudaStreamWaitEvent(s_side, e_fork, 0);
    k_gemm<<<gblocks, 256, SMEM_GEMM, s_side>>>(feat, nullptr, W1, ybf);
    cudaEventRecord(e_join, s_side);

    // CSR build on main stream (memsets replace k_init)
    cudaMemsetAsync(degp, 0, NN * sizeof(int), 0);
    cudaMemsetAsync(gstartp, 0x7f, (NG + 1) * sizeof(int), 0);
    k_deg<<<(NE / 4 + 255) / 256, 256>>>(dst);
    k_scan_a<<<SCAN_NB, SCAN_BLK>>>(gid);
    k_scan_c<<<SCAN_NB, SCAN_BLK>>>();
    k_scatter<<<(NE / 4 + 255) / 256, 256>>>(src, dst);

    // join: agg1 needs both CSR and ybf
    cudaStreamWaitEvent(0, e_join, 0);
    k_agg<<<(NN * 16 + 255) / 256, 256>>>(ybf, b1, hbf);

    // layer 2
    k_gemm<<<gblocks, 256, SMEM_GEMM>>>(nullptr, hbf, W2, ybf);
    k_agg<<<(NN * 16 + 255) / 256, 256>>>(ybf, b2, hbf);

    // pooling + decoder
    k_pool1<<<NG * 8, 512>>>(hbf);
    k_dec<<<NG, 128>>>(Wd1, bd1, Wd2, bd2, out);
}

// round 7
// speedup vs baseline: 4.1380x; 1.0101x over previous
#include <cuda_runtime.h>
#include <cuda_bf16.h>
#include <cstdint>

#define NN 100000
#define NE 1600000
#define F  128
#define NG 64
#define OUTF 64

#define SCAN_BLK 1024
#define SCAN_NB  ((NN + SCAN_BLK - 1) / SCAN_BLK)   // 98
#define FLAGBIT  0x40000000

// ---------------- scratch ----------------
__device__ __nv_bfloat16 g_ybf[NN * F];       // Y = X@W (bf16)
__device__ __nv_bfloat16 g_hbf[NN * F];       // layer output H (bf16)
__device__ int   g_degbuf[NN + SCAN_NB];      // [0,NN)=deg, [NN,NN+98)=block sums (one memset)
__device__ int   g_rowoff[NN + 1];
__device__ int   g_cursor[NN];
__device__ int   g_csr[NE];
__device__ float g_invdeg[NN];
__device__ int   g_gstart[NG + 1];
__device__ float g_part[NG * 8 * F];

// ---------------- CSR build ----------------
// g_degbuf zeroed via one cudaMemsetAsync; g_gstart init folded into k_deg.

__global__ void k_deg(const int* __restrict__ dst) {
    int t = blockIdx.x * blockDim.x + threadIdx.x;
    if (t <= NG) g_gstart[t] = 0x7f7f7f7f;     // sentinel; fixed up in k_scatter
    if (t < NE / 4) {
        int4 d = reinterpret_cast<const int4*>(dst)[t];
        atomicAdd(&g_degbuf[d.x], 1);
        atomicAdd(&g_degbuf[d.y], 1);
        atomicAdd(&g_degbuf[d.z], 1);
        atomicAdd(&g_degbuf[d.w], 1);
    }
}

// single-pass exclusive scan over degrees (warp-shuffle + predecessor lookback)
// + graph boundary detection (gid sorted). 98 blocks, all co-resident.
__global__ void k_scan(const int* __restrict__ gid) {
    int tid = threadIdx.x;
    int bid = blockIdx.x;
    int lane = tid & 31;
    int wid = tid >> 5;
    int i = bid * SCAN_BLK + tid;

    int v = (i < NN) ? g_degbuf[i] : 0;
    if (i < NN) {
        int g = gid[i];
        if (i == 0 || gid[i - 1] != g) g_gstart[g] = i;
    }

    // warp inclusive scan
    int x = v;
#pragma unroll
    for (int o = 1; o < 32; o <<= 1) {
        int y = __shfl_up_sync(0xFFFFFFFFu, x, o);
        if (lane >= o) x += y;
    }
    __shared__ int wsum[32];
    if (lane == 31) wsum[wid] = x;
    __syncthreads();
    if (wid == 0) {
        int w = wsum[lane];
#pragma unroll
        for (int o = 1; o < 32; o <<= 1) {
            int y = __shfl_up_sync(0xFFFFFFFFu, w, o);
            if (lane >= o) w += y;
        }
        wsum[lane] = w;
    }
    __syncthreads();
    int incl = x + (wid ? wsum[wid - 1] : 0);
    int blocktotal = wsum[31];

    // publish this block's aggregate (value|flag in one word: atomic, no fence needed)
    if (tid == 0) atomicExch(&g_degbuf[NN + bid], blocktotal | FLAGBIT);

    // lookback: warp 0 polls all predecessor aggregates
    __shared__ int s_prefix;
    if (wid == 0) {
        int sum = 0;
        for (int t = lane; t < bid; t += 32) {
            int val;
            do { val = atomicAdd(&g_degbuf[NN + t], 0); } while (!(val & FLAGBIT));
            sum += val & ~FLAGBIT;
        }
#pragma unroll
        for (int o = 16; o >= 1; o >>= 1) sum += __shfl_xor_sync(0xFFFFFFFFu, sum, o);
        if (lane == 0) s_prefix = sum;
    }
    __syncthreads();

    if (i < NN) {
        int r = s_prefix + incl - v;          // global exclusive prefix
        g_rowoff[i] = r;
        g_cursor[i] = r;
        g_invdeg[i] = 1.0f / (float)max(v, 1);
    }
    if (i == 0) g_rowoff[NN] = NE;
}

__global__ void k_scatter(const int* __restrict__ src, const int* __restrict__ dst) {
    int t = blockIdx.x * blockDim.x + threadIdx.x;
    // gstart suffix-min fixup for empty graphs (one thread, overlaps atomics)
    if (blockIdx.x == 0 && threadIdx.x == 0) {
        g_gstart[NG] = NN;
        for (int g = NG - 1; g >= 0; g--) {
            int nx = g_gstart[g + 1];
            if (g_gstart[g] > nx) g_gstart[g] = nx;
        }
    }
    if (t < NE / 4) {
        int4 d = reinterpret_cast<const int4*>(dst)[t];
        int4 s = reinterpret_cast<const int4*>(src)[t];
        int p0 = atomicAdd(&g_cursor[d.x], 1);
        int p1 = atomicAdd(&g_cursor[d.y], 1);
        int p2 = atomicAdd(&g_cursor[d.z], 1);
        int p3 = atomicAdd(&g_cursor[d.w], 1);
        g_csr[p0] = s.x;
        g_csr[p1] = s.y;
        g_csr[p2] = s.z;
        g_csr[p3] = s.w;
    }
}

// ---------------- tensor-core GEMM: Ybf = bf16( X @ W ) ----------------
#define PITCHB 272
#define ATILE_BYTES (256 * PITCHB)
#define BTILE_BYTES (128 * PITCHB)
#define SMEM_GEMM (ATILE_BYTES + 2 * BTILE_BYTES)  // 139264

__device__ __forceinline__ void ldsm_x4(uint32_t addr, uint32_t& r0, uint32_t& r1,
                                        uint32_t& r2, uint32_t& r3) {
    asm volatile("ldmatrix.sync.aligned.m8n8.x4.shared.b16 {%0,%1,%2,%3}, [%4];"
                 : "=r"(r0), "=r"(r1), "=r"(r2), "=r"(r3) : "r"(addr));
}
__device__ __forceinline__ void ldsm_x4t(uint32_t addr, uint32_t& r0, uint32_t& r1,
                                         uint32_t& r2, uint32_t& r3) {
    asm volatile("ldmatrix.sync.aligned.m8n8.x4.trans.shared.b16 {%0,%1,%2,%3}, [%4];"
                 : "=r"(r0), "=r"(r1), "=r"(r2), "=r"(r3) : "r"(addr));
}
__device__ __forceinline__ void mma_bf16(float& c0, float& c1, float& c2, float& c3,
                                         uint32_t a0, uint32_t a1, uint32_t a2, uint32_t a3,
                                         uint32_t b0, uint32_t b1) {
    asm volatile("mma.sync.aligned.m16n8k16.row.col.f32.bf16.bf16.f32 "
                 "{%0,%1,%2,%3},{%4,%5,%6,%7},{%8,%9},{%0,%1,%2,%3};"
                 : "+f"(c0), "+f"(c1), "+f"(c2), "+f"(c3)
                 : "r"(a0), "r"(a1), "r"(a2), "r"(a3), "r"(b0), "r"(b1));
}
__device__ __forceinline__ uint32_t pack2(float x, float y) {
    __nv_bfloat162 h = __floats2bfloat162_rn(x, y);
    return *reinterpret_cast<uint32_t*>(&h);
}
__device__ __forceinline__ uint32_t pack2lo(float x, float y, uint32_t hp) {
    float hx = __uint_as_float((hp & 0xFFFFu) << 16);
    float hy = __uint_as_float(hp & 0xFFFF0000u);
    __nv_bfloat162 h = __floats2bfloat162_rn(x - hx, y - hy);
    return *reinterpret_cast<uint32_t*>(&h);
}

__global__ __launch_bounds__(256, 1) void k_gemm(const float* __restrict__ Xf,
                                                 const __nv_bfloat16* __restrict__ Xb,
                                                 const float* __restrict__ W,
                                                 __nv_bfloat16* __restrict__ Ybf) {
    extern __shared__ char smem[];
    char* sA   = smem;
    char* sBhi = smem + ATILE_BYTES;
    char* sBlo = smem + ATILE_BYTES + BTILE_BYTES;

    int tid = threadIdx.x;
    int base = blockIdx.x * 256;

    for (int it = tid; it < 256 * 32; it += 256) {
        int row = it >> 5;
        int c4 = (it & 31) * 4;
        int r = min(base + row, NN - 1);
        uint2 a;
        if (Xb) {
            a = reinterpret_cast<const uint2*>(Xb)[(size_t)r * 32 + (c4 >> 2)];
        } else {
            float4 v = *reinterpret_cast<const float4*>(Xf + (size_t)r * F + c4);
            a = make_uint2(pack2(v.x, v.y), pack2(v.z, v.w));
        }
        *reinterpret_cast<uint2*>(sA + row * PITCHB + c4 * 2) = a;
    }
    for (int it = tid; it < 128 * 32; it += 256) {
        int row = it >> 5;
        int c4 = (it & 31) * 4;
        float4 v = *reinterpret_cast<const float4*>(W + row * F + c4);
        uint32_t h0 = pack2(v.x, v.y), h1 = pack2(v.z, v.w);
        uint32_t l0 = pack2lo(v.x, v.y, h0), l1 = pack2lo(v.z, v.w, h1);
        *reinterpret_cast<uint2*>(sBhi + row * PITCHB + c4 * 2) = make_uint2(h0, h1);
        *reinterpret_cast<uint2*>(sBlo + row * PITCHB + c4 * 2) = make_uint2(l0, l1);
    }
    __syncthreads();

    int lane = tid & 31;
    int w = tid >> 5;
    int m0 = w * 32;

    uint32_t sA_u   = (uint32_t)__cvta_generic_to_shared(sA);
    uint32_t sBhi_u = (uint32_t)__cvta_generic_to_shared(sBhi);
    uint32_t sBlo_u = (uint32_t)__cvta_generic_to_shared(sBlo);

    uint32_t arow = (uint32_t)((lane & 7) + ((lane >> 3) & 1) * 8);
    uint32_t aoff0 = (uint32_t)((m0 + arow) * PITCHB + (lane >> 4) * 16);
    uint32_t aoff1 = aoff0 + 16 * PITCHB;
    uint32_t boff = (uint32_t)((lane & 15) * PITCHB + (lane >> 4) * 16);

    float acc[2][16][4];
#pragma unroll
    for (int t = 0; t < 2; t++)
#pragma unroll
        for (int j = 0; j < 16; j++)
#pragma unroll
            for (int q = 0; q < 4; q++) acc[t][j][q] = 0.0f;

#pragma unroll
    for (int s = 0; s < 8; s++) {
        uint32_t a00, a01, a02, a03, a10, a11, a12, a13;
        ldsm_x4(sA_u + aoff0 + s * 32, a00, a01, a02, a03);
        ldsm_x4(sA_u + aoff1 + s * 32, a10, a11, a12, a13);
        uint32_t bbase = boff + s * 16 * PITCHB;
#pragma unroll
        for (int j2 = 0; j2 < 8; j2++) {
            int j = j2 * 2;
            uint32_t bh0, bh1, bh2, bh3, bl0, bl1, bl2, bl3;
            ldsm_x4t(sBhi_u + bbase + j2 * 32, bh0, bh1, bh2, bh3);
            mma_bf16(acc[0][j][0], acc[0][j][1], acc[0][j][2], acc[0][j][3],
                     a00, a01, a02, a03, bh0, bh1);
            mma_bf16(acc[1][j][0], acc[1][j][1], acc[1][j][2], acc[1][j][3],
                     a10, a11, a12, a13, bh0, bh1);
            mma_bf16(acc[0][j+1][0], acc[0][j+1][1], acc[0][j+1][2], acc[0][j+1][3],
                     a00, a01, a02, a03, bh2, bh3);
            mma_bf16(acc[1][j+1][0], acc[1][j+1][1], acc[1][j+1][2], acc[1][j+1][3],
                     a10, a11, a12, a13, bh2, bh3);
            ldsm_x4t(sBlo_u + bbase + j2 * 32, bl0, bl1, bl2, bl3);
            mma_bf16(acc[0][j][0], acc[0][j][1], acc[0][j][2], acc[0][j][3],
                     a00, a01, a02, a03, bl0, bl1);
            mma_bf16(acc[1][j][0], acc[1][j][1], acc[1][j][2], acc[1][j][3],
                     a10, a11, a12, a13, bl0, bl1);
            mma_bf16(acc[0][j+1][0], acc[0][j+1][1], acc[0][j+1][2], acc[0][j+1][3],
                     a00, a01, a02, a03, bl2, bl3);
            mma_bf16(acc[1][j+1][0], acc[1][j+1][1], acc[1][j+1][2], acc[1][j+1][3],
                     a10, a11, a12, a13, bl2, bl3);
        }
    }

    int gq = lane >> 2;
    int tq = lane & 3;
#pragma unroll
    for (int t = 0; t < 2; t++) {
        int r0 = base + m0 + t * 16 + gq;
        int r1 = r0 + 8;
#pragma unroll
        for (int j = 0; j < 16; j++) {
            int col = j * 8 + tq * 2;
            if (r0 < NN)
                *reinterpret_cast<uint32_t*>(Ybf + (size_t)r0 * F + col) =
                    pack2(acc[t][j][0], acc[t][j][1]);
            if (r1 < NN)
                *reinterpret_cast<uint32_t*>(Ybf + (size_t)r1 * F + col) =
                    pack2(acc[t][j][2], acc[t][j][3]);
        }
    }
}

// ---------------- aggregation: half-warp (16 lanes) per node, LDG.128 ------
__device__ __forceinline__ float bfl(uint32_t x) { return __uint_as_float(x << 16); }
__device__ __forceinline__ float bfh(uint32_t x) { return __uint_as_float(x & 0xFFFF0000u); }

__device__ __forceinline__ void acc8(float a[8], uint4 u) {
    a[0] += bfl(u.x); a[1] += bfh(u.x);
    a[2] += bfl(u.y); a[3] += bfh(u.y);
    a[4] += bfl(u.z); a[5] += bfh(u.z);
    a[6] += bfl(u.w); a[7] += bfh(u.w);
}

__global__ __launch_bounds__(256) void k_agg(const __nv_bfloat16* __restrict__ Ybf,
                                             const float* __restrict__ bias,
                                             __nv_bfloat16* __restrict__ Hbf) {
    int node   = (blockIdx.x * blockDim.x + threadIdx.x) >> 4;
    int lane16 = threadIdx.x & 15;
    if (node >= NN) return;

    int beg = g_rowoff[node];
    int end = g_rowoff[node + 1];
    const uint4* __restrict__ Yb4 = reinterpret_cast<const uint4*>(Ybf);

    float a[8];
#pragma unroll
    for (int q = 0; q < 8; q++) a[q] = 0.0f;

    int e = beg;
    for (; e + 7 < end; e += 8) {
        int s0 = g_csr[e],     s1 = g_csr[e + 1], s2 = g_csr[e + 2], s3 = g_csr[e + 3];
        int s4 = g_csr[e + 4], s5 = g_csr[e + 5], s6 = g_csr[e + 6], s7 = g_csr[e + 7];
        uint4 u0 = Yb4[(size_t)s0 * 16 + lane16];
        uint4 u1 = Yb4[(size_t)s1 * 16 + lane16];
        uint4 u2 = Yb4[(size_t)s2 * 16 + lane16];
        uint4 u3 = Yb4[(size_t)s3 * 16 + lane16];
        uint4 u4 = Yb4[(size_t)s4 * 16 + lane16];
        uint4 u5 = Yb4[(size_t)s5 * 16 + lane16];
        uint4 u6 = Yb4[(size_t)s6 * 16 + lane16];
        uint4 u7 = Yb4[(size_t)s7 * 16 + lane16];
        acc8(a, u0); acc8(a, u1); acc8(a, u2); acc8(a, u3);
        acc8(a, u4); acc8(a, u5); acc8(a, u6); acc8(a, u7);
    }
    for (; e + 3 < end; e += 4) {
        int s0 = g_csr[e], s1 = g_csr[e + 1], s2 = g_csr[e + 2], s3 = g_csr[e + 3];
        uint4 u0 = Yb4[(size_t)s0 * 16 + lane16];
        uint4 u1 = Yb4[(size_t)s1 * 16 + lane16];
        uint4 u2 = Yb4[(size_t)s2 * 16 + lane16];
        uint4 u3 = Yb4[(size_t)s3 * 16 + lane16];
        acc8(a, u0); acc8(a, u1); acc8(a, u2); acc8(a, u3);
    }
    for (; e < end; e++) {
        uint4 u = Yb4[(size_t)g_csr[e] * 16 + lane16];
        acc8(a, u);
    }

    float inv = g_invdeg[node];
    uint4 us = Yb4[(size_t)node * 16 + lane16];
    float s0 = bfl(us.x), s1 = bfh(us.x), s2 = bfl(us.y), s3 = bfh(us.y);
    float s4 = bfl(us.z), s5 = bfh(us.z), s6 = bfl(us.w), s7 = bfh(us.w);
    const float4* __restrict__ b4 = reinterpret_cast<const float4*>(bias);
    float4 bb0 = b4[lane16 * 2];
    float4 bb1 = b4[lane16 * 2 + 1];
    float h0 = fmaxf(fmaf(a[0], inv, s0) + bb0.x, 0.f);
    float h1 = fmaxf(fmaf(a[1], inv, s1) + bb0.y, 0.f);
    float h2 = fmaxf(fmaf(a[2], inv, s2) + bb0.z, 0.f);
    float h3 = fmaxf(fmaf(a[3], inv, s3) + bb0.w, 0.f);
    float h4 = fmaxf(fmaf(a[4], inv, s4) + bb1.x, 0.f);
    float h5 = fmaxf(fmaf(a[5], inv, s5) + bb1.y, 0.f);
    float h6 = fmaxf(fmaf(a[6], inv, s6) + bb1.z, 0.f);
    float h7 = fmaxf(fmaf(a[7], inv, s7) + bb1.w, 0.f);
    reinterpret_cast<uint4*>(Hbf)[(size_t)node * 16 + lane16] =
        make_uint4(pack2(h0, h1), pack2(h2, h3), pack2(h4, h5), pack2(h6, h7));
}

// ---------------- pooling stage 1 ----------------
__global__ void k_pool1(const __nv_bfloat16* __restrict__ H) {
    int bx = blockIdx.x;            // NG*8 blocks
    int g = bx >> 3, c = bx & 7;
    int tid = threadIdx.x;          // 512
    int col2 = tid & 63;
    int sub = tid >> 6;             // 0..7
    int s = g_gstart[g];
    int e = g_gstart[g + 1];
    const uint32_t* __restrict__ H2 = reinterpret_cast<const uint32_t*>(H);
    float px = 0.f, py = 0.f;
    for (int r = s + c * 8 + sub; r < e; r += 64) {
        uint32_t u = H2[(size_t)r * 64 + col2];
        px += bfl(u);
        py += bfh(u);
    }
    __shared__ float smx[512], smy[512];
    smx[tid] = px;
    smy[tid] = py;
    __syncthreads();
    if (tid < 64) {
        float sx = 0.f, sy = 0.f;
#pragma unroll
        for (int k = 0; k < 8; k++) {
            sx += smx[k * 64 + tid];
            sy += smy[k * 64 + tid];
        }
        *reinterpret_cast<float2*>(&g_part[bx * F + tid * 2]) = make_float2(sx, sy);
    }
}

// ---------------- pooling finalize + decoder (fused) ----------------
__global__ void k_dec(const float* __restrict__ Wd1, const float* __restrict__ bd1,
                      const float* __restrict__ Wd2, const float* __restrict__ bd2,
                      float* __restrict__ out) {
    int g = blockIdx.x;
    int tid = threadIdx.x;          // 128
    __shared__ float hgs[F], ts[F];

    float s = 0.f;
#pragma unroll
    for (int c = 0; c < 8; c++) s += g_part[(g * 8 + c) * F + tid];
    int cnt = g_gstart[g + 1] - g_gstart[g];
    float mean = s / (float)max(cnt, 1);
    out[g * F + tid] = mean;
    hgs[tid] = mean;
    __syncthreads();

    float s0 = 0.f, s1 = 0.f, s2 = 0.f, s3 = 0.f;
#pragma unroll 8
    for (int k = 0; k < F; k += 4) {
        s0 = fmaf(hgs[k],     Wd1[(k)     * F + tid], s0);
        s1 = fmaf(hgs[k + 1], Wd1[(k + 1) * F + tid], s1);
        s2 = fmaf(hgs[k + 2], Wd1[(k + 2) * F + tid], s2);
        s3 = fmaf(hgs[k + 3], Wd1[(k + 3) * F + tid], s3);
    }
    ts[tid] = fmaxf((s0 + s1) + (s2 + s3) + bd1[tid], 0.f);
    __syncthreads();
    if (tid < OUTF) {
        float o0 = 0.f, o1 = 0.f, o2 = 0.f, o3 = 0.f;
#pragma unroll 8
        for (int k = 0; k < F; k += 4) {
            o0 = fmaf(ts[k],     Wd2[(k)     * OUTF + tid], o0);
            o1 = fmaf(ts[k + 1], Wd2[(k + 1) * OUTF + tid], o1);
            o2 = fmaf(ts[k + 2], Wd2[(k + 2) * OUTF + tid], o2);
            o3 = fmaf(ts[k + 3], Wd2[(k + 3) * OUTF + tid], o3);
        }
        out[NG * F + g * OUTF + tid] = (o0 + o1) + (o2 + o3) + bd2[tid];
    }
}

// ---------------- launch ----------------
extern "C" void kernel_launch(void* const* d_in, const int* in_sizes, int n_in,
                              void* d_out, int out_size) {
    const float* feat = (const float*)d_in[0];
    const int*   src  = (const int*)d_in[1];
    const int*   dst  = (const int*)d_in[2];
    const int*   gid  = (const int*)d_in[3];
    const float* W1   = (const float*)d_in[4];
    const float* b1   = (const float*)d_in[5];
    const float* W2   = (const float*)d_in[6];
    const float* b2   = (const float*)d_in[7];
    const float* Wd1  = (const float*)d_in[8];
    const float* bd1  = (const float*)d_in[9];
    const float* Wd2  = (const float*)d_in[10];
    const float* bd2  = (const float*)d_in[11];
    float* out = (float*)d_out;

    __nv_bfloat16 *ybf, *hbf;
    void* degp;
    cudaGetSymbolAddress((void**)&ybf, g_ybf);
    cudaGetSymbolAddress((void**)&hbf, g_hbf);
    cudaGetSymbolAddress(&degp, g_degbuf);

    cudaFuncSetAttribute(k_gemm, cudaFuncAttributeMaxDynamicSharedMemorySize, SMEM_GEMM);

    static cudaStream_t s_side = nullptr;
    static cudaEvent_t e_fork = nullptr, e_join = nullptr;
    if (s_side == nullptr) {
        cudaStreamCreateWithFlags(&s_side, cudaStreamNonBlocking);
        cudaEventCreateWithFlags(&e_fork, cudaEventDisableTiming);
        cudaEventCreateWithFlags(&e_join, cudaEventDisableTiming);
    }

    int gblocks = (NN + 255) / 256;

    // fork: GEMM1 overlaps the CSR build
    cudaEventRecord(e_fork, 0);
    cudaStreamWaitEvent(s_side, e_fork, 0);
    k_gemm<<<gblocks, 256, SMEM_GEMM, s_side>>>(feat, nullptr, W1, ybf);
    cudaEventRecord(e_join, s_side);

    // CSR build on main stream (one memset covers deg + scan block sums)
    cudaMemsetAsync(degp, 0, (NN + SCAN_NB) * sizeof(int), 0);
    k_deg<<<(NE / 4 + 255) / 256, 256>>>(dst);
    k_scan<<<SCAN_NB, SCAN_BLK>>>(gid);
    k_scatter<<<(NE / 4 + 255) / 256, 256>>>(src, dst);

    // join: agg1 needs both CSR and ybf
    cudaStreamWaitEvent(0, e_join, 0);
    k_agg<<<(NN * 16 + 255) / 256, 256>>>(ybf, b1, hbf);

    // layer 2
    k_gemm<<<gblocks, 256, SMEM_GEMM>>>(nullptr, hbf, W2, ybf);
    k_agg<<<(NN * 16 + 255) / 256, 256>>>(ybf, b2, hbf);

    // pooling + decoder
    k_pool1<<<NG * 8, 512>>>(hbf);
    k_dec<<<NG, 128>>>(Wd1, bd1, Wd2, bd2, out);
}